// round 11
// baseline (speedup 1.0000x reference)
#include <cuda_runtime.h>
#include <cuda_fp16.h>
#include <math.h>
#include <stdint.h>

#define N_TOK 8192
#define DDIM  1024
#define NEXP  8
#define HDIM  2048
#define KSEL  2
#define NASN  (N_TOK*KSEL)
#define PADROWS 17408
#define MAX_TILES 160

// Output layout (flat concat of reference tuple, float32)
#define OUT_OFF 0
#define AUX_OFF 8388608
#define P_OFF   8388609
#define I_OFF   8454145
#define Q_OFF   8470529

// ---------------- scratch (static device globals; ~140 MiB total) -----------
__device__ __half g_Hh[(size_t)PADROWS * HDIM];    // 68 MiB (H, fp16 hi)
__device__ float  g_Ybuf[(size_t)PADROWS * DDIM];  // 68 MiB
__device__ float  g_partial[1024 * NEXP];
__device__ int    g_count[NEXP];
__device__ int    g_cursor[NEXP];
__device__ int    g_tokE[NASN];
__device__ float  g_tokQ[NASN];
__device__ int    g_assign[PADROWS];
__device__ int    g_t2p[NASN];
__device__ int    g_tileE[MAX_TILES];
__device__ int    g_tileR[MAX_TILES];
__device__ int    g_numTiles;

// ---------------- helpers ----------------------------------------------------
__device__ __forceinline__ uint32_t smem_u32(const void* p) {
    uint32_t a;
    asm("{ .reg .u64 t; cvta.to.shared.u64 t, %1; cvt.u32.u64 %0, t; }" : "=r"(a) : "l"(p));
    return a;
}

#define LDMX4(r0, r1, r2, r3, addr) \
    asm volatile("ldmatrix.sync.aligned.m8n8.x4.shared.b16 {%0,%1,%2,%3}, [%4];" \
        : "=r"(r0), "=r"(r1), "=r"(r2), "=r"(r3) : "r"(addr))

#define LDMX4T(r0, r1, r2, r3, addr) \
    asm volatile("ldmatrix.sync.aligned.m8n8.x4.trans.shared.b16 {%0,%1,%2,%3}, [%4];" \
        : "=r"(r0), "=r"(r1), "=r"(r2), "=r"(r3) : "r"(addr))

#define MMA(d0, d1, d2, d3, a0, a1, a2, a3, b0, b1) \
    asm volatile("mma.sync.aligned.m16n8k16.row.col.f32.f16.f16.f32 " \
        "{%0,%1,%2,%3}, {%4,%5,%6,%7}, {%8,%9}, {%0,%1,%2,%3};" \
        : "+f"(d0), "+f"(d1), "+f"(d2), "+f"(d3) \
        : "r"(a0), "r"(a1), "r"(a2), "r"(a3), "r"(b0), "r"(b1))

#define PACK2(r, vlo, vhi) \
    asm("cvt.rn.f16x2.f32 %0, %1, %2;" : "=r"(r) : "f"(vhi), "f"(vlo))

__device__ __forceinline__ void pack_hi4(float4 v, uint32_t& h0, uint32_t& h1) {
    PACK2(h0, v.x, v.y);
    PACK2(h1, v.z, v.w);
}
__device__ __forceinline__ void split_pack(float4 v,
        uint32_t& h0, uint32_t& h1, uint32_t& l0, uint32_t& l1) {
    PACK2(h0, v.x, v.y);
    PACK2(h1, v.z, v.w);
    __half2 ha = *(__half2*)&h0;
    __half2 hb = *(__half2*)&h1;
    float2 fa = __half22float2(ha);
    float2 fb = __half22float2(hb);
    PACK2(l0, v.x - fa.x, v.y - fa.y);
    PACK2(l1, v.z - fb.x, v.w - fb.y);
}
__device__ __forceinline__ float gelu_exact(float v) {
    return 0.5f * v * (1.0f + erff(v * 0.7071067811865476f));
}

// ---------------- 0: init ----------------------------------------------------
__global__ void k_init() {
    int i = blockIdx.x * 256 + threadIdx.x;
    if (i < NEXP) g_count[i] = 0;
    if (i < PADROWS) g_assign[i] = 0;
}

// ---------------- 1: router --------------------------------------------------
__global__ void k_router(const float* __restrict__ x,
                         const float* __restrict__ gw,
                         float* __restrict__ out) {
    __shared__ float sp[8][NEXP];
    int warp = threadIdx.x >> 5, lane = threadIdx.x & 31;
    int n = blockIdx.x * 8 + warp;
    const float* xr = x + (size_t)n * DDIM;

    float acc[NEXP];
#pragma unroll
    for (int e = 0; e < NEXP; e++) acc[e] = 0.f;
    for (int d = lane; d < DDIM; d += 32) {
        float xv = xr[d];
        float4 g0 = *(const float4*)(gw + d * NEXP);
        float4 g1 = *(const float4*)(gw + d * NEXP + 4);
        acc[0] = fmaf(xv, g0.x, acc[0]); acc[1] = fmaf(xv, g0.y, acc[1]);
        acc[2] = fmaf(xv, g0.z, acc[2]); acc[3] = fmaf(xv, g0.w, acc[3]);
        acc[4] = fmaf(xv, g1.x, acc[4]); acc[5] = fmaf(xv, g1.y, acc[5]);
        acc[6] = fmaf(xv, g1.z, acc[6]); acc[7] = fmaf(xv, g1.w, acc[7]);
    }
#pragma unroll
    for (int off = 16; off; off >>= 1)
#pragma unroll
        for (int e = 0; e < NEXP; e++)
            acc[e] += __shfl_down_sync(0xffffffffu, acc[e], off);

    if (lane == 0) {
        float mx = acc[0];
#pragma unroll
        for (int e = 1; e < NEXP; e++) mx = fmaxf(mx, acc[e]);
        float p[NEXP], s = 0.f;
#pragma unroll
        for (int e = 0; e < NEXP; e++) { p[e] = expf(acc[e] - mx); s += p[e]; }
        float inv = 1.f / s;
#pragma unroll
        for (int e = 0; e < NEXP; e++) {
            p[e] *= inv;
            out[P_OFF + (size_t)n * NEXP + e] = p[e];
            sp[warp][e] = p[e];
        }
        int b0 = 0; float v0 = p[0];
#pragma unroll
        for (int e = 1; e < NEXP; e++) if (p[e] > v0) { v0 = p[e]; b0 = e; }
        int b1 = -1; float v1 = -1.f;
#pragma unroll
        for (int e = 0; e < NEXP; e++) if (e != b0 && p[e] > v1) { v1 = p[e]; b1 = e; }
        float qs = 1.f / (v0 + v1);
        float q0 = v0 * qs, q1 = v1 * qs;
        out[I_OFF + n * 2 + 0] = (float)b0;
        out[I_OFF + n * 2 + 1] = (float)b1;
        out[Q_OFF + n * 2 + 0] = q0;
        out[Q_OFF + n * 2 + 1] = q1;
        g_tokE[n * 2 + 0] = b0;  g_tokE[n * 2 + 1] = b1;
        g_tokQ[n * 2 + 0] = q0;  g_tokQ[n * 2 + 1] = q1;
        atomicAdd(&g_count[b0], 1);
        atomicAdd(&g_count[b1], 1);
    }
    __syncthreads();
    if (warp == 0 && lane < NEXP) {
        float s = 0.f;
#pragma unroll
        for (int w = 0; w < 8; w++) s += sp[w][lane];
        g_partial[blockIdx.x * NEXP + lane] = s;
    }
}

// ---------------- 2: setup ---------------------------------------------------
__global__ void k_setup(float* __restrict__ out) {
    __shared__ float red[32][NEXP];
    __shared__ float auxp[NEXP];
    int t = threadIdx.x;
    {
        int e = t & 7, chunk = t >> 3;
        float s = 0.f;
        for (int b = 0; b < 32; b++) s += g_partial[(chunk * 32 + b) * NEXP + e];
        red[chunk][e] = s;
    }
    if (t == 0) {
        int off = 0, nt = 0;
        for (int e = 0; e < NEXP; e++) {
            g_cursor[e] = off;
            int tiles = (g_count[e] + 127) >> 7;
            for (int r = 0; r < tiles; r++) { g_tileE[nt] = e; g_tileR[nt] = off + r * 128; nt++; }
            off += tiles * 128;
        }
        g_numTiles = nt;
    }
    __syncthreads();
    if (t < NEXP) {
        float s = 0.f;
        for (int c = 0; c < 32; c++) s += red[c][t];
        float mean = s / (float)N_TOK;
        float frac = (float)g_count[t] / (float)N_TOK;
        auxp[t] = frac * mean;
    }
    __syncthreads();
    if (t == 0) {
        float s = 0.f;
        for (int e = 0; e < NEXP; e++) s += auxp[e];
        out[AUX_OFF] = (float)NEXP * s;
    }
}

// ---------------- 3: scatter -------------------------------------------------
__global__ void k_scatter() {
    int n = blockIdx.x * 256 + threadIdx.x;
    if (n >= N_TOK) return;
#pragma unroll
    for (int k = 0; k < KSEL; k++) {
        int e = g_tokE[n * 2 + k];
        int pos = atomicAdd(&g_cursor[e], 1);
        g_assign[pos] = n;
        g_t2p[n * 2 + k] = pos;
    }
}

// ---------------- 4: 2-term fp16 mma.sync grouped GEMM -----------------------
// C ~= Ah*(Bh+Bl). A (activations) fp16-hi only; B (weights) split in-loop.
// Phase 1: A = x (fp32, inline hi-pack). Phase 2: A = g_Hh (fp16, direct STS;
// zero conversion). NO cp.async anywhere (every cp.async kernel tripped the
// harness memory guard; every non-cp.async kernel passed).
#define RS       80
#define BRS      272
#define A_T      (128 * RS)          // 10240 (hi only)
#define B_T      (32 * BRS)          // 8704
#define OFF_AH   0
#define OFF_BH   A_T
#define OFF_BL   (A_T + B_T)
#define STG      (A_T + 2 * B_T)     // 27648
#define SMEM_DYN (2 * STG)           // 55296

template<int PHASE>
__global__ void __launch_bounds__(256, 1)
k_mma(const float* __restrict__ x, const float* __restrict__ w) {
    constexpr int KDIM = (PHASE == 1) ? DDIM : HDIM;
    constexpr int NG   = (PHASE == 1) ? HDIM : DDIM;
    int tileIdx = blockIdx.y;
    if (tileIdx >= g_numTiles) return;

    extern __shared__ char smem[];
    __shared__ int aTok[128];
    uint32_t sb = smem_u32(smem);
    int tid = threadIdx.x, wid = tid >> 5, l = tid & 31;

    int e = g_tileE[tileIdx];
    int rowBase = g_tileR[tileIdx];
    int n0 = blockIdx.x * 128;

    if (PHASE == 1 && tid < 128) aTok[tid] = g_assign[rowBase + tid];
    __syncthreads();

    const float* Bg = w + (size_t)e * DDIM * HDIM + n0;

    // B loader geometry (fp32 source, split in-loop): 4 float4/thread/stage
    const float* bBase[4];
    uint32_t sB[4];
#pragma unroll
    for (int j = 0; j < 4; j++) {
        int lin = tid + j * 256;
        int kr = lin >> 5, nc4 = (lin & 31) << 2;
        bBase[j] = Bg + (size_t)kr * NG + nc4;
        sB[j] = kr * BRS + nc4 * 2;
    }

    // A loader geometry
    const float*  aBase[4];   // phase 1: fp32 x rows (gathered)
    uint32_t sA[4];
    const __half* aBaseH[2];  // phase 2: fp16 g_Hh rows (direct copy)
    uint32_t sA2[2];
    if (PHASE == 1) {
#pragma unroll
        for (int j = 0; j < 4; j++) {
            int lin = tid + j * 256;
            int r = lin >> 3, c4 = (lin & 7) << 2;
            aBase[j] = x + (size_t)aTok[r] * DDIM + c4;
            sA[j] = r * RS + c4 * 2;
        }
    } else {
#pragma unroll
        for (int j = 0; j < 2; j++) {
            int lin = tid + j * 256;
            int r = lin >> 2, c8 = (lin & 3) << 3;
            aBaseH[j] = g_Hh + (size_t)(rowBase + r) * HDIM + c8;
            sA2[j] = r * RS + c8 * 2;
        }
    }

    int warpRow = (wid >> 1) * 32;
    int warpCol = (wid & 1) * 64;

    float acc[2][8][4];
#pragma unroll
    for (int i = 0; i < 2; i++)
#pragma unroll
        for (int j = 0; j < 8; j++)
#pragma unroll
            for (int k = 0; k < 4; k++) acc[i][j][k] = 0.f;

    uint32_t aoffA = (warpRow + (l & 15)) * RS + ((l >> 4) << 4);
    uint32_t boffB = (l & 15) * BRS + ((l >> 4) << 4);

    const int S = KDIM / 32;

    float4 pa[4], pb[4];
    uint4  paU[2];
    // ---- prologue: load stage 0, convert+store into buf0 ----
    if (PHASE == 1) {
#pragma unroll
        for (int j = 0; j < 4; j++) pa[j] = *(const float4*)(aBase[j]);
    } else {
#pragma unroll
        for (int j = 0; j < 2; j++) paU[j] = *(const uint4*)(aBaseH[j]);
    }
#pragma unroll
    for (int j = 0; j < 4; j++) pb[j] = *(const float4*)(bBase[j]);

    if (PHASE == 1) {
#pragma unroll
        for (int j = 0; j < 4; j++) {
            uint32_t h0, h1;
            pack_hi4(pa[j], h0, h1);
            char* pH = smem + OFF_AH + sA[j];
            ((uint32_t*)pH)[0] = h0; ((uint32_t*)pH)[1] = h1;
        }
    } else {
#pragma unroll
        for (int j = 0; j < 2; j++)
            *(uint4*)(smem + OFF_AH + sA2[j]) = paU[j];
    }
#pragma unroll
    for (int j = 0; j < 4; j++) {
        uint32_t h0, h1, l0, l1;
        split_pack(pb[j], h0, h1, l0, l1);
        char* qH = smem + OFF_BH + sB[j];
        char* qL = smem + OFF_BL + sB[j];
        ((uint32_t*)qH)[0] = h0; ((uint32_t*)qH)[1] = h1;
        ((uint32_t*)qL)[0] = l0; ((uint32_t*)qL)[1] = l1;
    }
    __syncthreads();

    for (int i = 0; i < S; i++) {
        uint32_t stg = sb + (i & 1) * STG;
        char* nxt = smem + ((i + 1) & 1) * STG;

        // issue global loads for stage i+1 (latency hidden under MMAs below)
        if (i + 1 < S) {
            int k0 = (i + 1) * 32;
            if (PHASE == 1) {
#pragma unroll
                for (int j = 0; j < 4; j++) pa[j] = *(const float4*)(aBase[j] + k0);
            } else {
#pragma unroll
                for (int j = 0; j < 2; j++) paU[j] = *(const uint4*)(aBaseH[j] + k0);
            }
#pragma unroll
            for (int j = 0; j < 4; j++) pb[j] = *(const float4*)(bBase[j] + (size_t)k0 * NG);
        }

        // MMA on stage i
#pragma unroll
        for (int kh = 0; kh < 2; kh++) {
            uint32_t ah0[4], ah1[4];
            LDMX4(ah0[0], ah0[1], ah0[2], ah0[3], stg + OFF_AH + aoffA + kh * 32);
            LDMX4(ah1[0], ah1[1], ah1[2], ah1[3], stg + OFF_AH + aoffA + 16 * RS + kh * 32);
#pragma unroll
            for (int p = 0; p < 4; p++) {
                uint32_t bo = boffB + kh * (16 * BRS) + (warpCol + p * 16) * 2;
                uint32_t bh0, bh1, bh2, bh3, bl0, bl1, bl2, bl3;
                LDMX4T(bh0, bh1, bh2, bh3, stg + OFF_BH + bo);
                LDMX4T(bl0, bl1, bl2, bl3, stg + OFF_BL + bo);

                MMA(acc[0][2*p][0], acc[0][2*p][1], acc[0][2*p][2], acc[0][2*p][3],
                    ah0[0], ah0[1], ah0[2], ah0[3], bh0, bh1);
                MMA(acc[1][2*p][0], acc[1][2*p][1], acc[1][2*p][2], acc[1][2*p][3],
                    ah1[0], ah1[1], ah1[2], ah1[3], bh0, bh1);
                MMA(acc[0][2*p+1][0], acc[0][2*p+1][1], acc[0][2*p+1][2], acc[0][2*p+1][3],
                    ah0[0], ah0[1], ah0[2], ah0[3], bh2, bh3);
                MMA(acc[1][2*p+1][0], acc[1][2*p+1][1], acc[1][2*p+1][2], acc[1][2*p+1][3],
                    ah1[0], ah1[1], ah1[2], ah1[3], bh2, bh3);

                MMA(acc[0][2*p][0], acc[0][2*p][1], acc[0][2*p][2], acc[0][2*p][3],
                    ah0[0], ah0[1], ah0[2], ah0[3], bl0, bl1);
                MMA(acc[1][2*p][0], acc[1][2*p][1], acc[1][2*p][2], acc[1][2*p][3],
                    ah1[0], ah1[1], ah1[2], ah1[3], bl0, bl1);
                MMA(acc[0][2*p+1][0], acc[0][2*p+1][1], acc[0][2*p+1][2], acc[0][2*p+1][3],
                    ah0[0], ah0[1], ah0[2], ah0[3], bl2, bl3);
                MMA(acc[1][2*p+1][0], acc[1][2*p+1][1], acc[1][2*p+1][2], acc[1][2*p+1][3],
                    ah1[0], ah1[1], ah1[2], ah1[3], bl2, bl3);
            }
        }

        // convert + store stage i+1 into the other buffer
        if (i + 1 < S) {
            if (PHASE == 1) {
#pragma unroll
                for (int j = 0; j < 4; j++) {
                    uint32_t h0, h1;
                    pack_hi4(pa[j], h0, h1);
                    char* pH = nxt + OFF_AH + sA[j];
                    ((uint32_t*)pH)[0] = h0; ((uint32_t*)pH)[1] = h1;
                }
            } else {
#pragma unroll
                for (int j = 0; j < 2; j++)
                    *(uint4*)(nxt + OFF_AH + sA2[j]) = paU[j];
            }
#pragma unroll
            for (int j = 0; j < 4; j++) {
                uint32_t h0, h1, l0, l1;
                split_pack(pb[j], h0, h1, l0, l1);
                char* qH = nxt + OFF_BH + sB[j];
                char* qL = nxt + OFF_BL + sB[j];
                ((uint32_t*)qH)[0] = h0; ((uint32_t*)qH)[1] = h1;
                ((uint32_t*)qL)[0] = l0; ((uint32_t*)qL)[1] = l1;
            }
        }
        __syncthreads();
    }

    // epilogue
    int qrow = l >> 2, qcol = (l & 3) * 2;
#pragma unroll
    for (int mf = 0; mf < 2; mf++) {
        int r0 = rowBase + warpRow + mf * 16 + qrow;
#pragma unroll
        for (int nf = 0; nf < 8; nf++) {
            int col = n0 + warpCol + nf * 8 + qcol;
            float c0 = acc[mf][nf][0], c1 = acc[mf][nf][1];
            float c2 = acc[mf][nf][2], c3 = acc[mf][nf][3];
            if (PHASE == 1) {
                uint32_t hp;
                PACK2(hp, gelu_exact(c0), gelu_exact(c1));
                *(uint32_t*)(g_Hh + (size_t)r0 * HDIM + col) = hp;
                PACK2(hp, gelu_exact(c2), gelu_exact(c3));
                *(uint32_t*)(g_Hh + (size_t)(r0 + 8) * HDIM + col) = hp;
            } else {
                *(float2*)(g_Ybuf + (size_t)r0 * DDIM + col)       = make_float2(c0, c1);
                *(float2*)(g_Ybuf + (size_t)(r0 + 8) * DDIM + col) = make_float2(c2, c3);
            }
        }
    }
}

// ---------------- 5: combine -------------------------------------------------
__global__ void k_combine(float* __restrict__ out) {
    int n = blockIdx.x;
    int t = threadIdx.x;
    int p0 = g_t2p[n * 2 + 0], p1 = g_t2p[n * 2 + 1];
    float q0 = g_tokQ[n * 2 + 0], q1 = g_tokQ[n * 2 + 1];
    int c = t * 4;
    float4 y0 = *(const float4*)(g_Ybuf + (size_t)p0 * DDIM + c);
    float4 y1 = *(const float4*)(g_Ybuf + (size_t)p1 * DDIM + c);
    float4 o;
    o.x = q0 * y0.x + q1 * y1.x;
    o.y = q0 * y0.y + q1 * y1.y;
    o.z = q0 * y0.z + q1 * y1.z;
    o.w = q0 * y0.w + q1 * y1.w;
    *(float4*)(out + OUT_OFF + (size_t)n * DDIM + c) = o;
}

// ---------------- launch -----------------------------------------------------
extern "C" void kernel_launch(void* const* d_in, const int* in_sizes, int n_in,
                              void* d_out, int out_size) {
    const float* x  = (const float*)d_in[0];
    const float* gw = (const float*)d_in[1];
    const float* w1 = (const float*)d_in[2];
    const float* w2 = (const float*)d_in[3];
    float* out = (float*)d_out;

    cudaFuncSetAttribute(k_mma<1>, cudaFuncAttributeMaxDynamicSharedMemorySize, SMEM_DYN);
    cudaFuncSetAttribute(k_mma<2>, cudaFuncAttributeMaxDynamicSharedMemorySize, SMEM_DYN);

    k_init<<<(PADROWS + 255) / 256, 256>>>();
    k_router<<<1024, 256>>>(x, gw, out);
    k_setup<<<1, 256>>>(out);
    k_scatter<<<N_TOK / 256, 256>>>();
    k_mma<1><<<dim3(HDIM / 128, MAX_TILES), 256, SMEM_DYN>>>(x, w1);
    k_mma<2><<<dim3(DDIM / 128, MAX_TILES), 256, SMEM_DYN>>>(x, w2);
    k_combine<<<N_TOK, 256>>>(out);
}

// round 13
// speedup vs baseline: 1.1423x; 1.1423x over previous
#include <cuda_runtime.h>
#include <cuda_fp16.h>
#include <math.h>
#include <stdint.h>

#define N_TOK 8192
#define DDIM  1024
#define NEXP  8
#define HDIM  2048
#define KSEL  2
#define NASN  (N_TOK*KSEL)
#define PADROWS 17408
#define MAX_TILES 160

// Output layout (flat concat of reference tuple, float32)
#define OUT_OFF 0
#define AUX_OFF 8388608
#define P_OFF   8388609
#define I_OFF   8454145
#define Q_OFF   8470529

// ---------------- scratch (static device globals; ~140 MiB total) -----------
// NOTE: no weight-derived statics. Every round that declared pre-split weight
// arrays tripped the harness 256 MiB guard (6/6); every round without them
// passed (5/5). Keep this envelope.
__device__ __half g_Hh[(size_t)PADROWS * HDIM];    // 68 MiB (H, fp16 hi)
__device__ float  g_Ybuf[(size_t)PADROWS * DDIM];  // 68 MiB
__device__ float  g_partial[1024 * NEXP];
__device__ int    g_count[NEXP];
__device__ int    g_cursor[NEXP];
__device__ int    g_tokE[NASN];
__device__ float  g_tokQ[NASN];
__device__ int    g_assign[PADROWS];
__device__ int    g_t2p[NASN];
__device__ int    g_tileE[MAX_TILES];
__device__ int    g_tileR[MAX_TILES];
__device__ int    g_numTiles;

// ---------------- helpers ----------------------------------------------------
__device__ __forceinline__ uint32_t smem_u32(const void* p) {
    uint32_t a;
    asm("{ .reg .u64 t; cvta.to.shared.u64 t, %1; cvt.u32.u64 %0, t; }" : "=r"(a) : "l"(p));
    return a;
}

#define LDMX4(r0, r1, r2, r3, addr) \
    asm volatile("ldmatrix.sync.aligned.m8n8.x4.shared.b16 {%0,%1,%2,%3}, [%4];" \
        : "=r"(r0), "=r"(r1), "=r"(r2), "=r"(r3) : "r"(addr))

#define LDMX4T(r0, r1, r2, r3, addr) \
    asm volatile("ldmatrix.sync.aligned.m8n8.x4.trans.shared.b16 {%0,%1,%2,%3}, [%4];" \
        : "=r"(r0), "=r"(r1), "=r"(r2), "=r"(r3) : "r"(addr))

#define MMA(d0, d1, d2, d3, a0, a1, a2, a3, b0, b1) \
    asm volatile("mma.sync.aligned.m16n8k16.row.col.f32.f16.f16.f32 " \
        "{%0,%1,%2,%3}, {%4,%5,%6,%7}, {%8,%9}, {%0,%1,%2,%3};" \
        : "+f"(d0), "+f"(d1), "+f"(d2), "+f"(d3) \
        : "r"(a0), "r"(a1), "r"(a2), "r"(a3), "r"(b0), "r"(b1))

#define PACK2(r, vlo, vhi) \
    asm("cvt.rn.f16x2.f32 %0, %1, %2;" : "=r"(r) : "f"(vhi), "f"(vlo))

__device__ __forceinline__ void pack_hi4(float4 v, uint32_t& h0, uint32_t& h1) {
    PACK2(h0, v.x, v.y);
    PACK2(h1, v.z, v.w);
}
__device__ __forceinline__ void split_pack(float4 v,
        uint32_t& h0, uint32_t& h1, uint32_t& l0, uint32_t& l1) {
    PACK2(h0, v.x, v.y);
    PACK2(h1, v.z, v.w);
    __half2 ha = *(__half2*)&h0;
    __half2 hb = *(__half2*)&h1;
    float2 fa = __half22float2(ha);
    float2 fb = __half22float2(hb);
    PACK2(l0, v.x - fa.x, v.y - fa.y);
    PACK2(l1, v.z - fb.x, v.w - fb.y);
}
__device__ __forceinline__ float gelu_exact(float v) {
    return 0.5f * v * (1.0f + erff(v * 0.7071067811865476f));
}

// ---------------- 0: init ----------------------------------------------------
__global__ void k_init() {
    int i = blockIdx.x * 256 + threadIdx.x;
    if (i < NEXP) g_count[i] = 0;
    if (i < PADROWS) g_assign[i] = 0;
}

// ---------------- 1: router --------------------------------------------------
__global__ void k_router(const float* __restrict__ x,
                         const float* __restrict__ gw,
                         float* __restrict__ out) {
    __shared__ float sp[8][NEXP];
    int warp = threadIdx.x >> 5, lane = threadIdx.x & 31;
    int n = blockIdx.x * 8 + warp;
    const float* xr = x + (size_t)n * DDIM;

    float acc[NEXP];
#pragma unroll
    for (int e = 0; e < NEXP; e++) acc[e] = 0.f;
    for (int d = lane; d < DDIM; d += 32) {
        float xv = xr[d];
        float4 g0 = *(const float4*)(gw + d * NEXP);
        float4 g1 = *(const float4*)(gw + d * NEXP + 4);
        acc[0] = fmaf(xv, g0.x, acc[0]); acc[1] = fmaf(xv, g0.y, acc[1]);
        acc[2] = fmaf(xv, g0.z, acc[2]); acc[3] = fmaf(xv, g0.w, acc[3]);
        acc[4] = fmaf(xv, g1.x, acc[4]); acc[5] = fmaf(xv, g1.y, acc[5]);
        acc[6] = fmaf(xv, g1.z, acc[6]); acc[7] = fmaf(xv, g1.w, acc[7]);
    }
#pragma unroll
    for (int off = 16; off; off >>= 1)
#pragma unroll
        for (int e = 0; e < NEXP; e++)
            acc[e] += __shfl_down_sync(0xffffffffu, acc[e], off);

    if (lane == 0) {
        float mx = acc[0];
#pragma unroll
        for (int e = 1; e < NEXP; e++) mx = fmaxf(mx, acc[e]);
        float p[NEXP], s = 0.f;
#pragma unroll
        for (int e = 0; e < NEXP; e++) { p[e] = expf(acc[e] - mx); s += p[e]; }
        float inv = 1.f / s;
#pragma unroll
        for (int e = 0; e < NEXP; e++) {
            p[e] *= inv;
            out[P_OFF + (size_t)n * NEXP + e] = p[e];
            sp[warp][e] = p[e];
        }
        int b0 = 0; float v0 = p[0];
#pragma unroll
        for (int e = 1; e < NEXP; e++) if (p[e] > v0) { v0 = p[e]; b0 = e; }
        int b1 = -1; float v1 = -1.f;
#pragma unroll
        for (int e = 0; e < NEXP; e++) if (e != b0 && p[e] > v1) { v1 = p[e]; b1 = e; }
        float qs = 1.f / (v0 + v1);
        float q0 = v0 * qs, q1 = v1 * qs;
        out[I_OFF + n * 2 + 0] = (float)b0;
        out[I_OFF + n * 2 + 1] = (float)b1;
        out[Q_OFF + n * 2 + 0] = q0;
        out[Q_OFF + n * 2 + 1] = q1;
        g_tokE[n * 2 + 0] = b0;  g_tokE[n * 2 + 1] = b1;
        g_tokQ[n * 2 + 0] = q0;  g_tokQ[n * 2 + 1] = q1;
        atomicAdd(&g_count[b0], 1);
        atomicAdd(&g_count[b1], 1);
    }
    __syncthreads();
    if (warp == 0 && lane < NEXP) {
        float s = 0.f;
#pragma unroll
        for (int w = 0; w < 8; w++) s += sp[w][lane];
        g_partial[blockIdx.x * NEXP + lane] = s;
    }
}

// ---------------- 2: setup ---------------------------------------------------
__global__ void k_setup(float* __restrict__ out) {
    __shared__ float red[32][NEXP];
    __shared__ float auxp[NEXP];
    int t = threadIdx.x;
    {
        int e = t & 7, chunk = t >> 3;
        float s = 0.f;
        for (int b = 0; b < 32; b++) s += g_partial[(chunk * 32 + b) * NEXP + e];
        red[chunk][e] = s;
    }
    if (t == 0) {
        int off = 0, nt = 0;
        for (int e = 0; e < NEXP; e++) {
            g_cursor[e] = off;
            int tiles = (g_count[e] + 127) >> 7;
            for (int r = 0; r < tiles; r++) { g_tileE[nt] = e; g_tileR[nt] = off + r * 128; nt++; }
            off += tiles * 128;
        }
        g_numTiles = nt;
    }
    __syncthreads();
    if (t < NEXP) {
        float s = 0.f;
        for (int c = 0; c < 32; c++) s += red[c][t];
        float mean = s / (float)N_TOK;
        float frac = (float)g_count[t] / (float)N_TOK;
        auxp[t] = frac * mean;
    }
    __syncthreads();
    if (t == 0) {
        float s = 0.f;
        for (int e = 0; e < NEXP; e++) s += auxp[e];
        out[AUX_OFF] = (float)NEXP * s;
    }
}

// ---------------- 3: scatter -------------------------------------------------
__global__ void k_scatter() {
    int n = blockIdx.x * 256 + threadIdx.x;
    if (n >= N_TOK) return;
#pragma unroll
    for (int k = 0; k < KSEL; k++) {
        int e = g_tokE[n * 2 + k];
        int pos = atomicAdd(&g_cursor[e], 1);
        g_assign[pos] = n;
        g_t2p[n * 2 + k] = pos;
    }
}

// ---------------- 4: fp16 mma.sync grouped GEMM ------------------------------
// PHASE 1 (2-term): H = gelu(Ah(x) @ (W1h + W1l)).
// PHASE 2 (1-term): Y = Hh @ W2h  (W2 lo dropped; MMAs halve; loop is
// mma.sync-throughput-bound so this is the only remaining lever).
#define RS       80
#define BRS      272
#define A_T      (128 * RS)          // 10240 (hi only)
#define B_T      (32 * BRS)          // 8704
#define OFF_AH   0
#define OFF_BH   A_T
#define OFF_BL   (A_T + B_T)
#define STG      (A_T + 2 * B_T)     // 27648
#define SMEM_DYN (2 * STG)           // 55296

template<int PHASE>
__global__ void __launch_bounds__(256, 1)
k_mma(const float* __restrict__ x, const float* __restrict__ w) {
    constexpr int KDIM = (PHASE == 1) ? DDIM : HDIM;
    constexpr int NG   = (PHASE == 1) ? HDIM : DDIM;
    constexpr bool BLO = (PHASE == 1);    // keep B-lo term only in GEMM1
    int tileIdx = blockIdx.y;
    if (tileIdx >= g_numTiles) return;

    extern __shared__ char smem[];
    __shared__ int aTok[128];
    uint32_t sb = smem_u32(smem);
    int tid = threadIdx.x, wid = tid >> 5, l = tid & 31;

    int e = g_tileE[tileIdx];
    int rowBase = g_tileR[tileIdx];
    int n0 = blockIdx.x * 128;

    if (PHASE == 1 && tid < 128) aTok[tid] = g_assign[rowBase + tid];
    __syncthreads();

    const float* Bg = w + (size_t)e * DDIM * HDIM + n0;

    // B loader geometry (fp32 source): 4 float4/thread/stage
    const float* bBase[4];
    uint32_t sB[4];
#pragma unroll
    for (int j = 0; j < 4; j++) {
        int lin = tid + j * 256;
        int kr = lin >> 5, nc4 = (lin & 31) << 2;
        bBase[j] = Bg + (size_t)kr * NG + nc4;
        sB[j] = kr * BRS + nc4 * 2;
    }

    // A loader geometry
    const float*  aBase[4];   // phase 1: fp32 x rows (gathered)
    uint32_t sA[4];
    const __half* aBaseH[2];  // phase 2: fp16 g_Hh rows (direct copy)
    uint32_t sA2[2];
    if (PHASE == 1) {
#pragma unroll
        for (int j = 0; j < 4; j++) {
            int lin = tid + j * 256;
            int r = lin >> 3, c4 = (lin & 7) << 2;
            aBase[j] = x + (size_t)aTok[r] * DDIM + c4;
            sA[j] = r * RS + c4 * 2;
        }
    } else {
#pragma unroll
        for (int j = 0; j < 2; j++) {
            int lin = tid + j * 256;
            int r = lin >> 2, c8 = (lin & 3) << 3;
            aBaseH[j] = g_Hh + (size_t)(rowBase + r) * HDIM + c8;
            sA2[j] = r * RS + c8 * 2;
        }
    }

    int warpRow = (wid >> 1) * 32;
    int warpCol = (wid & 1) * 64;

    float acc[2][8][4];
#pragma unroll
    for (int i = 0; i < 2; i++)
#pragma unroll
        for (int j = 0; j < 8; j++)
#pragma unroll
            for (int k = 0; k < 4; k++) acc[i][j][k] = 0.f;

    uint32_t aoffA = (warpRow + (l & 15)) * RS + ((l >> 4) << 4);
    uint32_t boffB = (l & 15) * BRS + ((l >> 4) << 4);

    const int S = KDIM / 32;

    float4 pa[4], pb[4];
    uint4  paU[2];
    // ---- prologue: load stage 0, convert+store into buf0 ----
    if (PHASE == 1) {
#pragma unroll
        for (int j = 0; j < 4; j++) pa[j] = *(const float4*)(aBase[j]);
    } else {
#pragma unroll
        for (int j = 0; j < 2; j++) paU[j] = *(const uint4*)(aBaseH[j]);
    }
#pragma unroll
    for (int j = 0; j < 4; j++) pb[j] = *(const float4*)(bBase[j]);

    if (PHASE == 1) {
#pragma unroll
        for (int j = 0; j < 4; j++) {
            uint32_t h0, h1;
            pack_hi4(pa[j], h0, h1);
            char* pH = smem + OFF_AH + sA[j];
            ((uint32_t*)pH)[0] = h0; ((uint32_t*)pH)[1] = h1;
        }
    } else {
#pragma unroll
        for (int j = 0; j < 2; j++)
            *(uint4*)(smem + OFF_AH + sA2[j]) = paU[j];
    }
#pragma unroll
    for (int j = 0; j < 4; j++) {
        if (BLO) {
            uint32_t h0, h1, l0, l1;
            split_pack(pb[j], h0, h1, l0, l1);
            char* qH = smem + OFF_BH + sB[j];
            char* qL = smem + OFF_BL + sB[j];
            ((uint32_t*)qH)[0] = h0; ((uint32_t*)qH)[1] = h1;
            ((uint32_t*)qL)[0] = l0; ((uint32_t*)qL)[1] = l1;
        } else {
            uint32_t h0, h1;
            pack_hi4(pb[j], h0, h1);
            char* qH = smem + OFF_BH + sB[j];
            ((uint32_t*)qH)[0] = h0; ((uint32_t*)qH)[1] = h1;
        }
    }
    __syncthreads();

    for (int i = 0; i < S; i++) {
        uint32_t stg = sb + (i & 1) * STG;
        char* nxt = smem + ((i + 1) & 1) * STG;

        // issue global loads for stage i+1 (latency hidden under MMAs below)
        if (i + 1 < S) {
            int k0 = (i + 1) * 32;
            if (PHASE == 1) {
#pragma unroll
                for (int j = 0; j < 4; j++) pa[j] = *(const float4*)(aBase[j] + k0);
            } else {
#pragma unroll
                for (int j = 0; j < 2; j++) paU[j] = *(const uint4*)(aBaseH[j] + k0);
            }
#pragma unroll
            for (int j = 0; j < 4; j++) pb[j] = *(const float4*)(bBase[j] + (size_t)k0 * NG);
        }

        // MMA on stage i
#pragma unroll
        for (int kh = 0; kh < 2; kh++) {
            uint32_t ah0[4], ah1[4];
            LDMX4(ah0[0], ah0[1], ah0[2], ah0[3], stg + OFF_AH + aoffA + kh * 32);
            LDMX4(ah1[0], ah1[1], ah1[2], ah1[3], stg + OFF_AH + aoffA + 16 * RS + kh * 32);
#pragma unroll
            for (int p = 0; p < 4; p++) {
                uint32_t bo = boffB + kh * (16 * BRS) + (warpCol + p * 16) * 2;
                uint32_t bh0, bh1, bh2, bh3;
                LDMX4T(bh0, bh1, bh2, bh3, stg + OFF_BH + bo);

                MMA(acc[0][2*p][0], acc[0][2*p][1], acc[0][2*p][2], acc[0][2*p][3],
                    ah0[0], ah0[1], ah0[2], ah0[3], bh0, bh1);
                MMA(acc[1][2*p][0], acc[1][2*p][1], acc[1][2*p][2], acc[1][2*p][3],
                    ah1[0], ah1[1], ah1[2], ah1[3], bh0, bh1);
                MMA(acc[0][2*p+1][0], acc[0][2*p+1][1], acc[0][2*p+1][2], acc[0][2*p+1][3],
                    ah0[0], ah0[1], ah0[2], ah0[3], bh2, bh3);
                MMA(acc[1][2*p+1][0], acc[1][2*p+1][1], acc[1][2*p+1][2], acc[1][2*p+1][3],
                    ah1[0], ah1[1], ah1[2], ah1[3], bh2, bh3);

                if (BLO) {
                    uint32_t bl0, bl1, bl2, bl3;
                    LDMX4T(bl0, bl1, bl2, bl3, stg + OFF_BL + bo);
                    MMA(acc[0][2*p][0], acc[0][2*p][1], acc[0][2*p][2], acc[0][2*p][3],
                        ah0[0], ah0[1], ah0[2], ah0[3], bl0, bl1);
                    MMA(acc[1][2*p][0], acc[1][2*p][1], acc[1][2*p][2], acc[1][2*p][3],
                        ah1[0], ah1[1], ah1[2], ah1[3], bl0, bl1);
                    MMA(acc[0][2*p+1][0], acc[0][2*p+1][1], acc[0][2*p+1][2], acc[0][2*p+1][3],
                        ah0[0], ah0[1], ah0[2], ah0[3], bl2, bl3);
                    MMA(acc[1][2*p+1][0], acc[1][2*p+1][1], acc[1][2*p+1][2], acc[1][2*p+1][3],
                        ah1[0], ah1[1], ah1[2], ah1[3], bl2, bl3);
                }
            }
        }

        // convert + store stage i+1 into the other buffer
        if (i + 1 < S) {
            if (PHASE == 1) {
#pragma unroll
                for (int j = 0; j < 4; j++) {
                    uint32_t h0, h1;
                    pack_hi4(pa[j], h0, h1);
                    char* pH = nxt + OFF_AH + sA[j];
                    ((uint32_t*)pH)[0] = h0; ((uint32_t*)pH)[1] = h1;
                }
            } else {
#pragma unroll
                for (int j = 0; j < 2; j++)
                    *(uint4*)(nxt + OFF_AH + sA2[j]) = paU[j];
            }
#pragma unroll
            for (int j = 0; j < 4; j++) {
                if (BLO) {
                    uint32_t h0, h1, l0, l1;
                    split_pack(pb[j], h0, h1, l0, l1);
                    char* qH = nxt + OFF_BH + sB[j];
                    char* qL = nxt + OFF_BL + sB[j];
                    ((uint32_t*)qH)[0] = h0; ((uint32_t*)qH)[1] = h1;
                    ((uint32_t*)qL)[0] = l0; ((uint32_t*)qL)[1] = l1;
                } else {
                    uint32_t h0, h1;
                    pack_hi4(pb[j], h0, h1);
                    char* qH = nxt + OFF_BH + sB[j];
                    ((uint32_t*)qH)[0] = h0; ((uint32_t*)qH)[1] = h1;
                }
            }
        }
        __syncthreads();
    }

    // epilogue
    int qrow = l >> 2, qcol = (l & 3) * 2;
#pragma unroll
    for (int mf = 0; mf < 2; mf++) {
        int r0 = rowBase + warpRow + mf * 16 + qrow;
#pragma unroll
        for (int nf = 0; nf < 8; nf++) {
            int col = n0 + warpCol + nf * 8 + qcol;
            float c0 = acc[mf][nf][0], c1 = acc[mf][nf][1];
            float c2 = acc[mf][nf][2], c3 = acc[mf][nf][3];
            if (PHASE == 1) {
                uint32_t hp;
                PACK2(hp, gelu_exact(c0), gelu_exact(c1));
                *(uint32_t*)(g_Hh + (size_t)r0 * HDIM + col) = hp;
                PACK2(hp, gelu_exact(c2), gelu_exact(c3));
                *(uint32_t*)(g_Hh + (size_t)(r0 + 8) * HDIM + col) = hp;
            } else {
                *(float2*)(g_Ybuf + (size_t)r0 * DDIM + col)       = make_float2(c0, c1);
                *(float2*)(g_Ybuf + (size_t)(r0 + 8) * DDIM + col) = make_float2(c2, c3);
            }
        }
    }
}

// ---------------- 5: combine -------------------------------------------------
__global__ void k_combine(float* __restrict__ out) {
    int n = blockIdx.x;
    int t = threadIdx.x;
    int p0 = g_t2p[n * 2 + 0], p1 = g_t2p[n * 2 + 1];
    float q0 = g_tokQ[n * 2 + 0], q1 = g_tokQ[n * 2 + 1];
    int c = t * 4;
    float4 y0 = *(const float4*)(g_Ybuf + (size_t)p0 * DDIM + c);
    float4 y1 = *(const float4*)(g_Ybuf + (size_t)p1 * DDIM + c);
    float4 o;
    o.x = q0 * y0.x + q1 * y1.x;
    o.y = q0 * y0.y + q1 * y1.y;
    o.z = q0 * y0.z + q1 * y1.z;
    o.w = q0 * y0.w + q1 * y1.w;
    *(float4*)(out + OUT_OFF + (size_t)n * DDIM + c) = o;
}

// ---------------- launch -----------------------------------------------------
extern "C" void kernel_launch(void* const* d_in, const int* in_sizes, int n_in,
                              void* d_out, int out_size) {
    const float* x  = (const float*)d_in[0];
    const float* gw = (const float*)d_in[1];
    const float* w1 = (const float*)d_in[2];
    const float* w2 = (const float*)d_in[3];
    float* out = (float*)d_out;

    cudaFuncSetAttribute(k_mma<1>, cudaFuncAttributeMaxDynamicSharedMemorySize, SMEM_DYN);
    cudaFuncSetAttribute(k_mma<2>, cudaFuncAttributeMaxDynamicSharedMemorySize, SMEM_DYN);

    k_init<<<(PADROWS + 255) / 256, 256>>>();
    k_router<<<1024, 256>>>(x, gw, out);
    k_setup<<<1, 256>>>(out);
    k_scatter<<<N_TOK / 256, 256>>>();
    k_mma<1><<<dim3(HDIM / 128, MAX_TILES), 256, SMEM_DYN>>>(x, w1);
    k_mma<2><<<dim3(DDIM / 128, MAX_TILES), 256, SMEM_DYN>>>(x, w2);
    k_combine<<<N_TOK, 256>>>(out);
}

// round 14
// speedup vs baseline: 1.2884x; 1.1279x over previous
#include <cuda_runtime.h>
#include <cuda_fp16.h>
#include <math.h>
#include <stdint.h>

#define N_TOK 8192
#define DDIM  1024
#define NEXP  8
#define HDIM  2048
#define KSEL  2
#define NASN  (N_TOK*KSEL)
#define PADROWS 17408
#define MAX_TILES 160

// Output layout (flat concat of reference tuple, float32)
#define OUT_OFF 0
#define AUX_OFF 8388608
#define P_OFF   8388609
#define I_OFF   8454145
#define Q_OFF   8470529

// ---------------- scratch (static device globals; ~140 MiB total) -----------
// NOTE: no weight-derived statics (6/6 fails), no cp.async. Proven envelope.
__device__ __half g_Hh[(size_t)PADROWS * HDIM];    // 68 MiB (H, fp16 hi)
__device__ float  g_Ybuf[(size_t)PADROWS * DDIM];  // 68 MiB
__device__ float  g_partial[1024 * NEXP];
__device__ int    g_count[NEXP];
__device__ int    g_cursor[NEXP];
__device__ int    g_tokE[NASN];
__device__ float  g_tokQ[NASN];
__device__ int    g_assign[PADROWS];
__device__ int    g_t2p[NASN];
__device__ int    g_tileE[MAX_TILES];
__device__ int    g_tileR[MAX_TILES];
__device__ int    g_numTiles;

// ---------------- helpers ----------------------------------------------------
__device__ __forceinline__ uint32_t smem_u32(const void* p) {
    uint32_t a;
    asm("{ .reg .u64 t; cvta.to.shared.u64 t, %1; cvt.u32.u64 %0, t; }" : "=r"(a) : "l"(p));
    return a;
}

#define LDMX4(r0, r1, r2, r3, addr) \
    asm volatile("ldmatrix.sync.aligned.m8n8.x4.shared.b16 {%0,%1,%2,%3}, [%4];" \
        : "=r"(r0), "=r"(r1), "=r"(r2), "=r"(r3) : "r"(addr))

#define LDMX4T(r0, r1, r2, r3, addr) \
    asm volatile("ldmatrix.sync.aligned.m8n8.x4.trans.shared.b16 {%0,%1,%2,%3}, [%4];" \
        : "=r"(r0), "=r"(r1), "=r"(r2), "=r"(r3) : "r"(addr))

#define MMA(d0, d1, d2, d3, a0, a1, a2, a3, b0, b1) \
    asm volatile("mma.sync.aligned.m16n8k16.row.col.f32.f16.f16.f32 " \
        "{%0,%1,%2,%3}, {%4,%5,%6,%7}, {%8,%9}, {%0,%1,%2,%3};" \
        : "+f"(d0), "+f"(d1), "+f"(d2), "+f"(d3) \
        : "r"(a0), "r"(a1), "r"(a2), "r"(a3), "r"(b0), "r"(b1))

#define PACK2(r, vlo, vhi) \
    asm("cvt.rn.f16x2.f32 %0, %1, %2;" : "=r"(r) : "f"(vhi), "f"(vlo))

__device__ __forceinline__ void pack_hi4(float4 v, uint32_t& h0, uint32_t& h1) {
    PACK2(h0, v.x, v.y);
    PACK2(h1, v.z, v.w);
}
__device__ __forceinline__ float gelu_exact(float v) {
    return 0.5f * v * (1.0f + erff(v * 0.7071067811865476f));
}

// ---------------- 0: init ----------------------------------------------------
__global__ void k_init() {
    int i = blockIdx.x * 256 + threadIdx.x;
    if (i < NEXP) g_count[i] = 0;
    if (i < PADROWS) g_assign[i] = 0;
}

// ---------------- 1: router --------------------------------------------------
__global__ void k_router(const float* __restrict__ x,
                         const float* __restrict__ gw,
                         float* __restrict__ out) {
    __shared__ float sp[8][NEXP];
    int warp = threadIdx.x >> 5, lane = threadIdx.x & 31;
    int n = blockIdx.x * 8 + warp;
    const float* xr = x + (size_t)n * DDIM;

    float acc[NEXP];
#pragma unroll
    for (int e = 0; e < NEXP; e++) acc[e] = 0.f;
    for (int d = lane; d < DDIM; d += 32) {
        float xv = xr[d];
        float4 g0 = *(const float4*)(gw + d * NEXP);
        float4 g1 = *(const float4*)(gw + d * NEXP + 4);
        acc[0] = fmaf(xv, g0.x, acc[0]); acc[1] = fmaf(xv, g0.y, acc[1]);
        acc[2] = fmaf(xv, g0.z, acc[2]); acc[3] = fmaf(xv, g0.w, acc[3]);
        acc[4] = fmaf(xv, g1.x, acc[4]); acc[5] = fmaf(xv, g1.y, acc[5]);
        acc[6] = fmaf(xv, g1.z, acc[6]); acc[7] = fmaf(xv, g1.w, acc[7]);
    }
#pragma unroll
    for (int off = 16; off; off >>= 1)
#pragma unroll
        for (int e = 0; e < NEXP; e++)
            acc[e] += __shfl_down_sync(0xffffffffu, acc[e], off);

    if (lane == 0) {
        float mx = acc[0];
#pragma unroll
        for (int e = 1; e < NEXP; e++) mx = fmaxf(mx, acc[e]);
        float p[NEXP], s = 0.f;
#pragma unroll
        for (int e = 0; e < NEXP; e++) { p[e] = expf(acc[e] - mx); s += p[e]; }
        float inv = 1.f / s;
#pragma unroll
        for (int e = 0; e < NEXP; e++) {
            p[e] *= inv;
            out[P_OFF + (size_t)n * NEXP + e] = p[e];
            sp[warp][e] = p[e];
        }
        int b0 = 0; float v0 = p[0];
#pragma unroll
        for (int e = 1; e < NEXP; e++) if (p[e] > v0) { v0 = p[e]; b0 = e; }
        int b1 = -1; float v1 = -1.f;
#pragma unroll
        for (int e = 0; e < NEXP; e++) if (e != b0 && p[e] > v1) { v1 = p[e]; b1 = e; }
        float qs = 1.f / (v0 + v1);
        float q0 = v0 * qs, q1 = v1 * qs;
        out[I_OFF + n * 2 + 0] = (float)b0;
        out[I_OFF + n * 2 + 1] = (float)b1;
        out[Q_OFF + n * 2 + 0] = q0;
        out[Q_OFF + n * 2 + 1] = q1;
        g_tokE[n * 2 + 0] = b0;  g_tokE[n * 2 + 1] = b1;
        g_tokQ[n * 2 + 0] = q0;  g_tokQ[n * 2 + 1] = q1;
        atomicAdd(&g_count[b0], 1);
        atomicAdd(&g_count[b1], 1);
    }
    __syncthreads();
    if (warp == 0 && lane < NEXP) {
        float s = 0.f;
#pragma unroll
        for (int w = 0; w < 8; w++) s += sp[w][lane];
        g_partial[blockIdx.x * NEXP + lane] = s;
    }
}

// ---------------- 2: setup ---------------------------------------------------
__global__ void k_setup(float* __restrict__ out) {
    __shared__ float red[32][NEXP];
    __shared__ float auxp[NEXP];
    int t = threadIdx.x;
    {
        int e = t & 7, chunk = t >> 3;
        float s = 0.f;
        for (int b = 0; b < 32; b++) s += g_partial[(chunk * 32 + b) * NEXP + e];
        red[chunk][e] = s;
    }
    if (t == 0) {
        int off = 0, nt = 0;
        for (int e = 0; e < NEXP; e++) {
            g_cursor[e] = off;
            int tiles = (g_count[e] + 127) >> 7;
            for (int r = 0; r < tiles; r++) { g_tileE[nt] = e; g_tileR[nt] = off + r * 128; nt++; }
            off += tiles * 128;
        }
        g_numTiles = nt;
    }
    __syncthreads();
    if (t < NEXP) {
        float s = 0.f;
        for (int c = 0; c < 32; c++) s += red[c][t];
        float mean = s / (float)N_TOK;
        float frac = (float)g_count[t] / (float)N_TOK;
        auxp[t] = frac * mean;
    }
    __syncthreads();
    if (t == 0) {
        float s = 0.f;
        for (int e = 0; e < NEXP; e++) s += auxp[e];
        out[AUX_OFF] = (float)NEXP * s;
    }
}

// ---------------- 3: scatter -------------------------------------------------
__global__ void k_scatter() {
    int n = blockIdx.x * 256 + threadIdx.x;
    if (n >= N_TOK) return;
#pragma unroll
    for (int k = 0; k < KSEL; k++) {
        int e = g_tokE[n * 2 + k];
        int pos = atomicAdd(&g_cursor[e], 1);
        g_assign[pos] = n;
        g_t2p[n * 2 + k] = pos;
    }
}

// ---------------- 4: single-term fp16 mma.sync grouped GEMM ------------------
// Both phases: C ~= Ah @ Bh (plain fp16, fp32 accum; each dropped lo-term
// adds ~2e-4 rel_err in quadrature, total ~4.5e-4 << 1e-3 gate).
// 128x128x32 tiles, 8 warps, 32 HMMA/stage.
#define RS       80
#define BRS      272
#define A_T      (128 * RS)          // 10240
#define B_T      (32 * BRS)          // 8704
#define OFF_AH   0
#define OFF_BH   A_T
#define STG      (A_T + B_T)         // 18944
#define SMEM_DYN (2 * STG)           // 37888

template<int PHASE>
__global__ void __launch_bounds__(256, 1)
k_mma(const float* __restrict__ x, const float* __restrict__ w) {
    constexpr int KDIM = (PHASE == 1) ? DDIM : HDIM;
    constexpr int NG   = (PHASE == 1) ? HDIM : DDIM;
    int tileIdx = blockIdx.y;
    if (tileIdx >= g_numTiles) return;

    extern __shared__ char smem[];
    __shared__ int aTok[128];
    uint32_t sb = smem_u32(smem);
    int tid = threadIdx.x, wid = tid >> 5, l = tid & 31;

    int e = g_tileE[tileIdx];
    int rowBase = g_tileR[tileIdx];
    int n0 = blockIdx.x * 128;

    if (PHASE == 1 && tid < 128) aTok[tid] = g_assign[rowBase + tid];
    __syncthreads();

    const float* Bg = w + (size_t)e * DDIM * HDIM + n0;

    // B loader geometry (fp32 source, hi-pack in-loop): 4 float4/thread/stage
    const float* bBase[4];
    uint32_t sB[4];
#pragma unroll
    for (int j = 0; j < 4; j++) {
        int lin = tid + j * 256;
        int kr = lin >> 5, nc4 = (lin & 31) << 2;
        bBase[j] = Bg + (size_t)kr * NG + nc4;
        sB[j] = kr * BRS + nc4 * 2;
    }

    // A loader geometry
    const float*  aBase[4];   // phase 1: fp32 x rows (gathered)
    uint32_t sA[4];
    const __half* aBaseH[2];  // phase 2: fp16 g_Hh rows (direct copy)
    uint32_t sA2[2];
    if (PHASE == 1) {
#pragma unroll
        for (int j = 0; j < 4; j++) {
            int lin = tid + j * 256;
            int r = lin >> 3, c4 = (lin & 7) << 2;
            aBase[j] = x + (size_t)aTok[r] * DDIM + c4;
            sA[j] = r * RS + c4 * 2;
        }
    } else {
#pragma unroll
        for (int j = 0; j < 2; j++) {
            int lin = tid + j * 256;
            int r = lin >> 2, c8 = (lin & 3) << 3;
            aBaseH[j] = g_Hh + (size_t)(rowBase + r) * HDIM + c8;
            sA2[j] = r * RS + c8 * 2;
        }
    }

    int warpRow = (wid >> 1) * 32;
    int warpCol = (wid & 1) * 64;

    float acc[2][8][4];
#pragma unroll
    for (int i = 0; i < 2; i++)
#pragma unroll
        for (int j = 0; j < 8; j++)
#pragma unroll
            for (int k = 0; k < 4; k++) acc[i][j][k] = 0.f;

    uint32_t aoffA = (warpRow + (l & 15)) * RS + ((l >> 4) << 4);
    uint32_t boffB = (l & 15) * BRS + ((l >> 4) << 4);

    const int S = KDIM / 32;

    float4 pa[4], pb[4];
    uint4  paU[2];
    // ---- prologue: load stage 0, convert+store into buf0 ----
    if (PHASE == 1) {
#pragma unroll
        for (int j = 0; j < 4; j++) pa[j] = *(const float4*)(aBase[j]);
    } else {
#pragma unroll
        for (int j = 0; j < 2; j++) paU[j] = *(const uint4*)(aBaseH[j]);
    }
#pragma unroll
    for (int j = 0; j < 4; j++) pb[j] = *(const float4*)(bBase[j]);

    if (PHASE == 1) {
#pragma unroll
        for (int j = 0; j < 4; j++) {
            uint32_t h0, h1;
            pack_hi4(pa[j], h0, h1);
            char* pH = smem + OFF_AH + sA[j];
            ((uint32_t*)pH)[0] = h0; ((uint32_t*)pH)[1] = h1;
        }
    } else {
#pragma unroll
        for (int j = 0; j < 2; j++)
            *(uint4*)(smem + OFF_AH + sA2[j]) = paU[j];
    }
#pragma unroll
    for (int j = 0; j < 4; j++) {
        uint32_t h0, h1;
        pack_hi4(pb[j], h0, h1);
        char* qH = smem + OFF_BH + sB[j];
        ((uint32_t*)qH)[0] = h0; ((uint32_t*)qH)[1] = h1;
    }
    __syncthreads();

    for (int i = 0; i < S; i++) {
        uint32_t stg = sb + (i & 1) * STG;
        char* nxt = smem + ((i + 1) & 1) * STG;

        // issue global loads for stage i+1 (latency hidden under MMAs below)
        if (i + 1 < S) {
            int k0 = (i + 1) * 32;
            if (PHASE == 1) {
#pragma unroll
                for (int j = 0; j < 4; j++) pa[j] = *(const float4*)(aBase[j] + k0);
            } else {
#pragma unroll
                for (int j = 0; j < 2; j++) paU[j] = *(const uint4*)(aBaseH[j] + k0);
            }
#pragma unroll
            for (int j = 0; j < 4; j++) pb[j] = *(const float4*)(bBase[j] + (size_t)k0 * NG);
        }

        // MMA on stage i (single term: Ah x Bh)
#pragma unroll
        for (int kh = 0; kh < 2; kh++) {
            uint32_t ah0[4], ah1[4];
            LDMX4(ah0[0], ah0[1], ah0[2], ah0[3], stg + OFF_AH + aoffA + kh * 32);
            LDMX4(ah1[0], ah1[1], ah1[2], ah1[3], stg + OFF_AH + aoffA + 16 * RS + kh * 32);
#pragma unroll
            for (int p = 0; p < 4; p++) {
                uint32_t bo = boffB + kh * (16 * BRS) + (warpCol + p * 16) * 2;
                uint32_t bh0, bh1, bh2, bh3;
                LDMX4T(bh0, bh1, bh2, bh3, stg + OFF_BH + bo);

                MMA(acc[0][2*p][0], acc[0][2*p][1], acc[0][2*p][2], acc[0][2*p][3],
                    ah0[0], ah0[1], ah0[2], ah0[3], bh0, bh1);
                MMA(acc[1][2*p][0], acc[1][2*p][1], acc[1][2*p][2], acc[1][2*p][3],
                    ah1[0], ah1[1], ah1[2], ah1[3], bh0, bh1);
                MMA(acc[0][2*p+1][0], acc[0][2*p+1][1], acc[0][2*p+1][2], acc[0][2*p+1][3],
                    ah0[0], ah0[1], ah0[2], ah0[3], bh2, bh3);
                MMA(acc[1][2*p+1][0], acc[1][2*p+1][1], acc[1][2*p+1][2], acc[1][2*p+1][3],
                    ah1[0], ah1[1], ah1[2], ah1[3], bh2, bh3);
            }
        }

        // convert + store stage i+1 into the other buffer
        if (i + 1 < S) {
            if (PHASE == 1) {
#pragma unroll
                for (int j = 0; j < 4; j++) {
                    uint32_t h0, h1;
                    pack_hi4(pa[j], h0, h1);
                    char* pH = nxt + OFF_AH + sA[j];
                    ((uint32_t*)pH)[0] = h0; ((uint32_t*)pH)[1] = h1;
                }
            } else {
#pragma unroll
                for (int j = 0; j < 2; j++)
                    *(uint4*)(nxt + OFF_AH + sA2[j]) = paU[j];
            }
#pragma unroll
            for (int j = 0; j < 4; j++) {
                uint32_t h0, h1;
                pack_hi4(pb[j], h0, h1);
                char* qH = nxt + OFF_BH + sB[j];
                ((uint32_t*)qH)[0] = h0; ((uint32_t*)qH)[1] = h1;
            }
        }
        __syncthreads();
    }

    // epilogue
    int qrow = l >> 2, qcol = (l & 3) * 2;
#pragma unroll
    for (int mf = 0; mf < 2; mf++) {
        int r0 = rowBase + warpRow + mf * 16 + qrow;
#pragma unroll
        for (int nf = 0; nf < 8; nf++) {
            int col = n0 + warpCol + nf * 8 + qcol;
            float c0 = acc[mf][nf][0], c1 = acc[mf][nf][1];
            float c2 = acc[mf][nf][2], c3 = acc[mf][nf][3];
            if (PHASE == 1) {
                uint32_t hp;
                PACK2(hp, gelu_exact(c0), gelu_exact(c1));
                *(uint32_t*)(g_Hh + (size_t)r0 * HDIM + col) = hp;
                PACK2(hp, gelu_exact(c2), gelu_exact(c3));
                *(uint32_t*)(g_Hh + (size_t)(r0 + 8) * HDIM + col) = hp;
            } else {
                *(float2*)(g_Ybuf + (size_t)r0 * DDIM + col)       = make_float2(c0, c1);
                *(float2*)(g_Ybuf + (size_t)(r0 + 8) * DDIM + col) = make_float2(c2, c3);
            }
        }
    }
}

// ---------------- 5: combine -------------------------------------------------
__global__ void k_combine(float* __restrict__ out) {
    int n = blockIdx.x;
    int t = threadIdx.x;
    int p0 = g_t2p[n * 2 + 0], p1 = g_t2p[n * 2 + 1];
    float q0 = g_tokQ[n * 2 + 0], q1 = g_tokQ[n * 2 + 1];
    int c = t * 4;
    float4 y0 = *(const float4*)(g_Ybuf + (size_t)p0 * DDIM + c);
    float4 y1 = *(const float4*)(g_Ybuf + (size_t)p1 * DDIM + c);
    float4 o;
    o.x = q0 * y0.x + q1 * y1.x;
    o.y = q0 * y0.y + q1 * y1.y;
    o.z = q0 * y0.z + q1 * y1.z;
    o.w = q0 * y0.w + q1 * y1.w;
    *(float4*)(out + OUT_OFF + (size_t)n * DDIM + c) = o;
}

// ---------------- launch -----------------------------------------------------
extern "C" void kernel_launch(void* const* d_in, const int* in_sizes, int n_in,
                              void* d_out, int out_size) {
    const float* x  = (const float*)d_in[0];
    const float* gw = (const float*)d_in[1];
    const float* w1 = (const float*)d_in[2];
    const float* w2 = (const float*)d_in[3];
    float* out = (float*)d_out;

    cudaFuncSetAttribute(k_mma<1>, cudaFuncAttributeMaxDynamicSharedMemorySize, SMEM_DYN);
    cudaFuncSetAttribute(k_mma<2>, cudaFuncAttributeMaxDynamicSharedMemorySize, SMEM_DYN);

    k_init<<<(PADROWS + 255) / 256, 256>>>();
    k_router<<<1024, 256>>>(x, gw, out);
    k_setup<<<1, 256>>>(out);
    k_scatter<<<N_TOK / 256, 256>>>();
    k_mma<1><<<dim3(HDIM / 128, MAX_TILES), 256, SMEM_DYN>>>(x, w1);
    k_mma<2><<<dim3(DDIM / 128, MAX_TILES), 256, SMEM_DYN>>>(x, w2);
    k_combine<<<N_TOK, 256>>>(out);
}

// round 15
// speedup vs baseline: 1.6840x; 1.3071x over previous
#include <cuda_runtime.h>
#include <cuda_fp16.h>
#include <math.h>
#include <stdint.h>

#define N_TOK 8192
#define DDIM  1024
#define NEXP  8
#define HDIM  2048
#define KSEL  2
#define NASN  (N_TOK*KSEL)
#define PADROWS 17408
#define MAX_TILES 160

// Output layout (flat concat of reference tuple, float32)
#define OUT_OFF 0
#define AUX_OFF 8388608
#define P_OFF   8388609
#define I_OFF   8454145
#define Q_OFF   8470529

// ---------------- scratch (static device globals; ~140 MiB total) -----------
// NOTE: no weight-derived statics (6/6 fails), no cp.async. Proven envelope.
__device__ __half g_Hh[(size_t)PADROWS * HDIM];    // 68 MiB (H, fp16 hi)
__device__ float  g_Ybuf[(size_t)PADROWS * DDIM];  // 68 MiB
__device__ float  g_partial[1024 * NEXP];
__device__ int    g_count[NEXP];
__device__ int    g_cursor[NEXP];
__device__ int    g_tokE[NASN];
__device__ float  g_tokQ[NASN];
__device__ int    g_assign[PADROWS];
__device__ int    g_t2p[NASN];
__device__ int    g_tileE[MAX_TILES];
__device__ int    g_tileR[MAX_TILES];
__device__ int    g_numTiles;

// ---------------- helpers ----------------------------------------------------
__device__ __forceinline__ uint32_t smem_u32(const void* p) {
    uint32_t a;
    asm("{ .reg .u64 t; cvta.to.shared.u64 t, %1; cvt.u32.u64 %0, t; }" : "=r"(a) : "l"(p));
    return a;
}

#define LDMX4(r0, r1, r2, r3, addr) \
    asm volatile("ldmatrix.sync.aligned.m8n8.x4.shared.b16 {%0,%1,%2,%3}, [%4];" \
        : "=r"(r0), "=r"(r1), "=r"(r2), "=r"(r3) : "r"(addr))

#define LDMX4T(r0, r1, r2, r3, addr) \
    asm volatile("ldmatrix.sync.aligned.m8n8.x4.trans.shared.b16 {%0,%1,%2,%3}, [%4];" \
        : "=r"(r0), "=r"(r1), "=r"(r2), "=r"(r3) : "r"(addr))

#define MMA(d0, d1, d2, d3, a0, a1, a2, a3, b0, b1) \
    asm volatile("mma.sync.aligned.m16n8k16.row.col.f32.f16.f16.f32 " \
        "{%0,%1,%2,%3}, {%4,%5,%6,%7}, {%8,%9}, {%0,%1,%2,%3};" \
        : "+f"(d0), "+f"(d1), "+f"(d2), "+f"(d3) \
        : "r"(a0), "r"(a1), "r"(a2), "r"(a3), "r"(b0), "r"(b1))

#define PACK2(r, vlo, vhi) \
    asm("cvt.rn.f16x2.f32 %0, %1, %2;" : "=r"(r) : "f"(vhi), "f"(vlo))

__device__ __forceinline__ void pack_hi4(float4 v, uint32_t& h0, uint32_t& h1) {
    PACK2(h0, v.x, v.y);
    PACK2(h1, v.z, v.w);
}
__device__ __forceinline__ float gelu_exact(float v) {
    return 0.5f * v * (1.0f + erff(v * 0.7071067811865476f));
}

// ---------------- 0: init ----------------------------------------------------
__global__ void k_init() {
    int i = blockIdx.x * 256 + threadIdx.x;
    if (i < NEXP) g_count[i] = 0;
    if (i < PADROWS) g_assign[i] = 0;
}

// ---------------- 1: router --------------------------------------------------
__global__ void k_router(const float* __restrict__ x,
                         const float* __restrict__ gw,
                         float* __restrict__ out) {
    __shared__ float sp[8][NEXP];
    int warp = threadIdx.x >> 5, lane = threadIdx.x & 31;
    int n = blockIdx.x * 8 + warp;
    const float* xr = x + (size_t)n * DDIM;

    float acc[NEXP];
#pragma unroll
    for (int e = 0; e < NEXP; e++) acc[e] = 0.f;
    for (int d = lane; d < DDIM; d += 32) {
        float xv = xr[d];
        float4 g0 = *(const float4*)(gw + d * NEXP);
        float4 g1 = *(const float4*)(gw + d * NEXP + 4);
        acc[0] = fmaf(xv, g0.x, acc[0]); acc[1] = fmaf(xv, g0.y, acc[1]);
        acc[2] = fmaf(xv, g0.z, acc[2]); acc[3] = fmaf(xv, g0.w, acc[3]);
        acc[4] = fmaf(xv, g1.x, acc[4]); acc[5] = fmaf(xv, g1.y, acc[5]);
        acc[6] = fmaf(xv, g1.z, acc[6]); acc[7] = fmaf(xv, g1.w, acc[7]);
    }
#pragma unroll
    for (int off = 16; off; off >>= 1)
#pragma unroll
        for (int e = 0; e < NEXP; e++)
            acc[e] += __shfl_down_sync(0xffffffffu, acc[e], off);

    if (lane == 0) {
        float mx = acc[0];
#pragma unroll
        for (int e = 1; e < NEXP; e++) mx = fmaxf(mx, acc[e]);
        float p[NEXP], s = 0.f;
#pragma unroll
        for (int e = 0; e < NEXP; e++) { p[e] = expf(acc[e] - mx); s += p[e]; }
        float inv = 1.f / s;
#pragma unroll
        for (int e = 0; e < NEXP; e++) {
            p[e] *= inv;
            out[P_OFF + (size_t)n * NEXP + e] = p[e];
            sp[warp][e] = p[e];
        }
        int b0 = 0; float v0 = p[0];
#pragma unroll
        for (int e = 1; e < NEXP; e++) if (p[e] > v0) { v0 = p[e]; b0 = e; }
        int b1 = -1; float v1 = -1.f;
#pragma unroll
        for (int e = 0; e < NEXP; e++) if (e != b0 && p[e] > v1) { v1 = p[e]; b1 = e; }
        float qs = 1.f / (v0 + v1);
        float q0 = v0 * qs, q1 = v1 * qs;
        out[I_OFF + n * 2 + 0] = (float)b0;
        out[I_OFF + n * 2 + 1] = (float)b1;
        out[Q_OFF + n * 2 + 0] = q0;
        out[Q_OFF + n * 2 + 1] = q1;
        g_tokE[n * 2 + 0] = b0;  g_tokE[n * 2 + 1] = b1;
        g_tokQ[n * 2 + 0] = q0;  g_tokQ[n * 2 + 1] = q1;
        atomicAdd(&g_count[b0], 1);
        atomicAdd(&g_count[b1], 1);
    }
    __syncthreads();
    if (warp == 0 && lane < NEXP) {
        float s = 0.f;
#pragma unroll
        for (int w = 0; w < 8; w++) s += sp[w][lane];
        g_partial[blockIdx.x * NEXP + lane] = s;
    }
}

// ---------------- 2: setup ---------------------------------------------------
__global__ void k_setup(float* __restrict__ out) {
    __shared__ float red[32][NEXP];
    __shared__ float auxp[NEXP];
    int t = threadIdx.x;
    {
        int e = t & 7, chunk = t >> 3;
        float s = 0.f;
        for (int b = 0; b < 32; b++) s += g_partial[(chunk * 32 + b) * NEXP + e];
        red[chunk][e] = s;
    }
    if (t == 0) {
        int off = 0, nt = 0;
        for (int e = 0; e < NEXP; e++) {
            g_cursor[e] = off;
            int tiles = (g_count[e] + 127) >> 7;
            for (int r = 0; r < tiles; r++) { g_tileE[nt] = e; g_tileR[nt] = off + r * 128; nt++; }
            off += tiles * 128;
        }
        g_numTiles = nt;
    }
    __syncthreads();
    if (t < NEXP) {
        float s = 0.f;
        for (int c = 0; c < 32; c++) s += red[c][t];
        float mean = s / (float)N_TOK;
        float frac = (float)g_count[t] / (float)N_TOK;
        auxp[t] = frac * mean;
    }
    __syncthreads();
    if (t == 0) {
        float s = 0.f;
        for (int e = 0; e < NEXP; e++) s += auxp[e];
        out[AUX_OFF] = (float)NEXP * s;
    }
}

// ---------------- 3: scatter -------------------------------------------------
__global__ void k_scatter() {
    int n = blockIdx.x * 256 + threadIdx.x;
    if (n >= N_TOK) return;
#pragma unroll
    for (int k = 0; k < KSEL; k++) {
        int e = g_tokE[n * 2 + k];
        int pos = atomicAdd(&g_cursor[e], 1);
        g_assign[pos] = n;
        g_t2p[n * 2 + k] = pos;
    }
}

// ---------------- 4: single-term fp16 mma.sync grouped GEMM ------------------
// C ~= Ah @ Bh. 128x256x32 tiles (N widened to amortize per-stage overhead
// over 2x MMAs), 8 warps (4M x 2N), warp tile 32x128, 64 HMMA/warp/stage.
#define RS       80
#define BRS      528                 // 256 halves + 16B pad; 528 % 128 == 16
#define A_T      (128 * RS)          // 10240
#define B_T      (32 * BRS)          // 16896
#define OFF_AH   0
#define OFF_BH   A_T
#define STG      (A_T + B_T)         // 27136
#define SMEM_DYN (2 * STG)           // 54272

template<int PHASE>
__global__ void __launch_bounds__(256, 1)
k_mma(const float* __restrict__ x, const float* __restrict__ w) {
    constexpr int KDIM = (PHASE == 1) ? DDIM : HDIM;
    constexpr int NG   = (PHASE == 1) ? HDIM : DDIM;
    int tileIdx = blockIdx.y;
    if (tileIdx >= g_numTiles) return;

    extern __shared__ char smem[];
    __shared__ int aTok[128];
    uint32_t sb = smem_u32(smem);
    int tid = threadIdx.x, wid = tid >> 5, l = tid & 31;

    int e = g_tileE[tileIdx];
    int rowBase = g_tileR[tileIdx];
    int n0 = blockIdx.x * 256;

    if (PHASE == 1 && tid < 128) aTok[tid] = g_assign[rowBase + tid];
    __syncthreads();

    const float* Bg = w + (size_t)e * DDIM * HDIM + n0;

    // B loader geometry (fp32 source, hi-pack in-loop): 8 float4/thread/stage
    // 32 k-rows x 256 n-cols = 2048 float4; lin -> kr = lin>>6, nc4 = (lin&63)*4
    const float* bBase[8];
    uint32_t sB[8];
#pragma unroll
    for (int j = 0; j < 8; j++) {
        int lin = tid + j * 256;
        int kr = lin >> 6, nc4 = (lin & 63) << 2;
        bBase[j] = Bg + (size_t)kr * NG + nc4;
        sB[j] = kr * BRS + nc4 * 2;
    }

    // A loader geometry
    const float*  aBase[4];   // phase 1: fp32 x rows (gathered)
    uint32_t sA[4];
    const __half* aBaseH[2];  // phase 2: fp16 g_Hh rows (direct copy)
    uint32_t sA2[2];
    if (PHASE == 1) {
#pragma unroll
        for (int j = 0; j < 4; j++) {
            int lin = tid + j * 256;
            int r = lin >> 3, c4 = (lin & 7) << 2;
            aBase[j] = x + (size_t)aTok[r] * DDIM + c4;
            sA[j] = r * RS + c4 * 2;
        }
    } else {
#pragma unroll
        for (int j = 0; j < 2; j++) {
            int lin = tid + j * 256;
            int r = lin >> 2, c8 = (lin & 3) << 3;
            aBaseH[j] = g_Hh + (size_t)(rowBase + r) * HDIM + c8;
            sA2[j] = r * RS + c8 * 2;
        }
    }

    int warpRow = (wid >> 1) * 32;
    int warpCol = (wid & 1) * 128;

    float acc[2][16][4];
#pragma unroll
    for (int i = 0; i < 2; i++)
#pragma unroll
        for (int j = 0; j < 16; j++)
#pragma unroll
            for (int k = 0; k < 4; k++) acc[i][j][k] = 0.f;

    uint32_t aoffA = (warpRow + (l & 15)) * RS + ((l >> 4) << 4);
    uint32_t boffB = (l & 15) * BRS + ((l >> 4) << 4);

    const int S = KDIM / 32;

    float4 pa[4], pb[8];
    uint4  paU[2];
    // ---- prologue: load stage 0, convert+store into buf0 ----
    if (PHASE == 1) {
#pragma unroll
        for (int j = 0; j < 4; j++) pa[j] = *(const float4*)(aBase[j]);
    } else {
#pragma unroll
        for (int j = 0; j < 2; j++) paU[j] = *(const uint4*)(aBaseH[j]);
    }
#pragma unroll
    for (int j = 0; j < 8; j++) pb[j] = *(const float4*)(bBase[j]);

    if (PHASE == 1) {
#pragma unroll
        for (int j = 0; j < 4; j++) {
            uint32_t h0, h1;
            pack_hi4(pa[j], h0, h1);
            char* pH = smem + OFF_AH + sA[j];
            ((uint32_t*)pH)[0] = h0; ((uint32_t*)pH)[1] = h1;
        }
    } else {
#pragma unroll
        for (int j = 0; j < 2; j++)
            *(uint4*)(smem + OFF_AH + sA2[j]) = paU[j];
    }
#pragma unroll
    for (int j = 0; j < 8; j++) {
        uint32_t h0, h1;
        pack_hi4(pb[j], h0, h1);
        char* qH = smem + OFF_BH + sB[j];
        ((uint32_t*)qH)[0] = h0; ((uint32_t*)qH)[1] = h1;
    }
    __syncthreads();

    for (int i = 0; i < S; i++) {
        uint32_t stg = sb + (i & 1) * STG;
        char* nxt = smem + ((i + 1) & 1) * STG;

        // issue global loads for stage i+1 (latency hidden under MMAs below)
        if (i + 1 < S) {
            int k0 = (i + 1) * 32;
            if (PHASE == 1) {
#pragma unroll
                for (int j = 0; j < 4; j++) pa[j] = *(const float4*)(aBase[j] + k0);
            } else {
#pragma unroll
                for (int j = 0; j < 2; j++) paU[j] = *(const uint4*)(aBaseH[j] + k0);
            }
#pragma unroll
            for (int j = 0; j < 8; j++) pb[j] = *(const float4*)(bBase[j] + (size_t)k0 * NG);
        }

        // MMA on stage i (single term: Ah x Bh, warp tile 32x128)
#pragma unroll
        for (int kh = 0; kh < 2; kh++) {
            uint32_t ah0[4], ah1[4];
            LDMX4(ah0[0], ah0[1], ah0[2], ah0[3], stg + OFF_AH + aoffA + kh * 32);
            LDMX4(ah1[0], ah1[1], ah1[2], ah1[3], stg + OFF_AH + aoffA + 16 * RS + kh * 32);
#pragma unroll
            for (int p = 0; p < 8; p++) {
                uint32_t bo = boffB + kh * (16 * BRS) + (warpCol + p * 16) * 2;
                uint32_t bh0, bh1, bh2, bh3;
                LDMX4T(bh0, bh1, bh2, bh3, stg + OFF_BH + bo);

                MMA(acc[0][2*p][0], acc[0][2*p][1], acc[0][2*p][2], acc[0][2*p][3],
                    ah0[0], ah0[1], ah0[2], ah0[3], bh0, bh1);
                MMA(acc[1][2*p][0], acc[1][2*p][1], acc[1][2*p][2], acc[1][2*p][3],
                    ah1[0], ah1[1], ah1[2], ah1[3], bh0, bh1);
                MMA(acc[0][2*p+1][0], acc[0][2*p+1][1], acc[0][2*p+1][2], acc[0][2*p+1][3],
                    ah0[0], ah0[1], ah0[2], ah0[3], bh2, bh3);
                MMA(acc[1][2*p+1][0], acc[1][2*p+1][1], acc[1][2*p+1][2], acc[1][2*p+1][3],
                    ah1[0], ah1[1], ah1[2], ah1[3], bh2, bh3);
            }
        }

        // convert + store stage i+1 into the other buffer
        if (i + 1 < S) {
            if (PHASE == 1) {
#pragma unroll
                for (int j = 0; j < 4; j++) {
                    uint32_t h0, h1;
                    pack_hi4(pa[j], h0, h1);
                    char* pH = nxt + OFF_AH + sA[j];
                    ((uint32_t*)pH)[0] = h0; ((uint32_t*)pH)[1] = h1;
                }
            } else {
#pragma unroll
                for (int j = 0; j < 2; j++)
                    *(uint4*)(nxt + OFF_AH + sA2[j]) = paU[j];
            }
#pragma unroll
            for (int j = 0; j < 8; j++) {
                uint32_t h0, h1;
                pack_hi4(pb[j], h0, h1);
                char* qH = nxt + OFF_BH + sB[j];
                ((uint32_t*)qH)[0] = h0; ((uint32_t*)qH)[1] = h1;
            }
        }
        __syncthreads();
    }

    // epilogue
    int qrow = l >> 2, qcol = (l & 3) * 2;
#pragma unroll
    for (int mf = 0; mf < 2; mf++) {
        int r0 = rowBase + warpRow + mf * 16 + qrow;
#pragma unroll
        for (int nf = 0; nf < 16; nf++) {
            int col = n0 + warpCol + nf * 8 + qcol;
            float c0 = acc[mf][nf][0], c1 = acc[mf][nf][1];
            float c2 = acc[mf][nf][2], c3 = acc[mf][nf][3];
            if (PHASE == 1) {
                uint32_t hp;
                PACK2(hp, gelu_exact(c0), gelu_exact(c1));
                *(uint32_t*)(g_Hh + (size_t)r0 * HDIM + col) = hp;
                PACK2(hp, gelu_exact(c2), gelu_exact(c3));
                *(uint32_t*)(g_Hh + (size_t)(r0 + 8) * HDIM + col) = hp;
            } else {
                *(float2*)(g_Ybuf + (size_t)r0 * DDIM + col)       = make_float2(c0, c1);
                *(float2*)(g_Ybuf + (size_t)(r0 + 8) * DDIM + col) = make_float2(c2, c3);
            }
        }
    }
}

// ---------------- 5: combine -------------------------------------------------
__global__ void k_combine(float* __restrict__ out) {
    int n = blockIdx.x;
    int t = threadIdx.x;
    int p0 = g_t2p[n * 2 + 0], p1 = g_t2p[n * 2 + 1];
    float q0 = g_tokQ[n * 2 + 0], q1 = g_tokQ[n * 2 + 1];
    int c = t * 4;
    float4 y0 = *(const float4*)(g_Ybuf + (size_t)p0 * DDIM + c);
    float4 y1 = *(const float4*)(g_Ybuf + (size_t)p1 * DDIM + c);
    float4 o;
    o.x = q0 * y0.x + q1 * y1.x;
    o.y = q0 * y0.y + q1 * y1.y;
    o.z = q0 * y0.z + q1 * y1.z;
    o.w = q0 * y0.w + q1 * y1.w;
    *(float4*)(out + OUT_OFF + (size_t)n * DDIM + c) = o;
}

// ---------------- launch -----------------------------------------------------
extern "C" void kernel_launch(void* const* d_in, const int* in_sizes, int n_in,
                              void* d_out, int out_size) {
    const float* x  = (const float*)d_in[0];
    const float* gw = (const float*)d_in[1];
    const float* w1 = (const float*)d_in[2];
    const float* w2 = (const float*)d_in[3];
    float* out = (float*)d_out;

    cudaFuncSetAttribute(k_mma<1>, cudaFuncAttributeMaxDynamicSharedMemorySize, SMEM_DYN);
    cudaFuncSetAttribute(k_mma<2>, cudaFuncAttributeMaxDynamicSharedMemorySize, SMEM_DYN);

    k_init<<<(PADROWS + 255) / 256, 256>>>();
    k_router<<<1024, 256>>>(x, gw, out);
    k_setup<<<1, 256>>>(out);
    k_scatter<<<N_TOK / 256, 256>>>();
    k_mma<1><<<dim3(HDIM / 256, MAX_TILES), 256, SMEM_DYN>>>(x, w1);
    k_mma<2><<<dim3(DDIM / 256, MAX_TILES), 256, SMEM_DYN>>>(x, w2);
    k_combine<<<N_TOK, 256>>>(out);
}

// round 16
// speedup vs baseline: 1.6868x; 1.0017x over previous
#include <cuda_runtime.h>
#include <cuda_fp16.h>
#include <math.h>
#include <stdint.h>

#define N_TOK 8192
#define DDIM  1024
#define NEXP  8
#define HDIM  2048
#define KSEL  2
#define NASN  (N_TOK*KSEL)
#define PADROWS 17408
#define MAX_TILES 160

// Output layout (flat concat of reference tuple, float32)
#define OUT_OFF 0
#define AUX_OFF 8388608
#define P_OFF   8388609
#define I_OFF   8454145
#define Q_OFF   8470529

// ---------------- scratch (static device globals; ~140 MiB total) -----------
// NOTE: no weight-derived statics (6/6 fails), no cp.async. Proven envelope.
__device__ __half g_Hh[(size_t)PADROWS * HDIM];    // 68 MiB (H, fp16 hi)
__device__ float  g_Ybuf[(size_t)PADROWS * DDIM];  // 68 MiB
__device__ float  g_partial[1024 * NEXP];
__device__ int    g_count[NEXP];
__device__ int    g_cursor[NEXP];
__device__ int    g_tokE[NASN];
__device__ float  g_tokQ[NASN];
__device__ int    g_assign[PADROWS];
__device__ int    g_t2p[NASN];
__device__ int    g_tileE[MAX_TILES];
__device__ int    g_tileR[MAX_TILES];
__device__ int    g_numTiles;

// ---------------- helpers ----------------------------------------------------
__device__ __forceinline__ uint32_t smem_u32(const void* p) {
    uint32_t a;
    asm("{ .reg .u64 t; cvta.to.shared.u64 t, %1; cvt.u32.u64 %0, t; }" : "=r"(a) : "l"(p));
    return a;
}

#define LDMX4(r0, r1, r2, r3, addr) \
    asm volatile("ldmatrix.sync.aligned.m8n8.x4.shared.b16 {%0,%1,%2,%3}, [%4];" \
        : "=r"(r0), "=r"(r1), "=r"(r2), "=r"(r3) : "r"(addr))

#define LDMX4T(r0, r1, r2, r3, addr) \
    asm volatile("ldmatrix.sync.aligned.m8n8.x4.trans.shared.b16 {%0,%1,%2,%3}, [%4];" \
        : "=r"(r0), "=r"(r1), "=r"(r2), "=r"(r3) : "r"(addr))

#define MMA(d0, d1, d2, d3, a0, a1, a2, a3, b0, b1) \
    asm volatile("mma.sync.aligned.m16n8k16.row.col.f32.f16.f16.f32 " \
        "{%0,%1,%2,%3}, {%4,%5,%6,%7}, {%8,%9}, {%0,%1,%2,%3};" \
        : "+f"(d0), "+f"(d1), "+f"(d2), "+f"(d3) \
        : "r"(a0), "r"(a1), "r"(a2), "r"(a3), "r"(b0), "r"(b1))

#define PACK2(r, vlo, vhi) \
    asm("cvt.rn.f16x2.f32 %0, %1, %2;" : "=r"(r) : "f"(vhi), "f"(vlo))

__device__ __forceinline__ void pack_hi4(float4 v, uint32_t& h0, uint32_t& h1) {
    PACK2(h0, v.x, v.y);
    PACK2(h1, v.z, v.w);
}
__device__ __forceinline__ float gelu_exact(float v) {
    return 0.5f * v * (1.0f + erff(v * 0.7071067811865476f));
}

// ---------------- 0: init ----------------------------------------------------
__global__ void k_init() {
    int i = blockIdx.x * 256 + threadIdx.x;
    if (i < NEXP) g_count[i] = 0;
    if (i < PADROWS) g_assign[i] = 0;
}

// ---------------- 1: router --------------------------------------------------
__global__ void k_router(const float* __restrict__ x,
                         const float* __restrict__ gw,
                         float* __restrict__ out) {
    __shared__ float sp[8][NEXP];
    int warp = threadIdx.x >> 5, lane = threadIdx.x & 31;
    int n = blockIdx.x * 8 + warp;
    const float* xr = x + (size_t)n * DDIM;

    float acc[NEXP];
#pragma unroll
    for (int e = 0; e < NEXP; e++) acc[e] = 0.f;
    for (int d = lane; d < DDIM; d += 32) {
        float xv = xr[d];
        float4 g0 = *(const float4*)(gw + d * NEXP);
        float4 g1 = *(const float4*)(gw + d * NEXP + 4);
        acc[0] = fmaf(xv, g0.x, acc[0]); acc[1] = fmaf(xv, g0.y, acc[1]);
        acc[2] = fmaf(xv, g0.z, acc[2]); acc[3] = fmaf(xv, g0.w, acc[3]);
        acc[4] = fmaf(xv, g1.x, acc[4]); acc[5] = fmaf(xv, g1.y, acc[5]);
        acc[6] = fmaf(xv, g1.z, acc[6]); acc[7] = fmaf(xv, g1.w, acc[7]);
    }
#pragma unroll
    for (int off = 16; off; off >>= 1)
#pragma unroll
        for (int e = 0; e < NEXP; e++)
            acc[e] += __shfl_down_sync(0xffffffffu, acc[e], off);

    if (lane == 0) {
        float mx = acc[0];
#pragma unroll
        for (int e = 1; e < NEXP; e++) mx = fmaxf(mx, acc[e]);
        float p[NEXP], s = 0.f;
#pragma unroll
        for (int e = 0; e < NEXP; e++) { p[e] = expf(acc[e] - mx); s += p[e]; }
        float inv = 1.f / s;
#pragma unroll
        for (int e = 0; e < NEXP; e++) {
            p[e] *= inv;
            out[P_OFF + (size_t)n * NEXP + e] = p[e];
            sp[warp][e] = p[e];
        }
        int b0 = 0; float v0 = p[0];
#pragma unroll
        for (int e = 1; e < NEXP; e++) if (p[e] > v0) { v0 = p[e]; b0 = e; }
        int b1 = -1; float v1 = -1.f;
#pragma unroll
        for (int e = 0; e < NEXP; e++) if (e != b0 && p[e] > v1) { v1 = p[e]; b1 = e; }
        float qs = 1.f / (v0 + v1);
        float q0 = v0 * qs, q1 = v1 * qs;
        out[I_OFF + n * 2 + 0] = (float)b0;
        out[I_OFF + n * 2 + 1] = (float)b1;
        out[Q_OFF + n * 2 + 0] = q0;
        out[Q_OFF + n * 2 + 1] = q1;
        g_tokE[n * 2 + 0] = b0;  g_tokE[n * 2 + 1] = b1;
        g_tokQ[n * 2 + 0] = q0;  g_tokQ[n * 2 + 1] = q1;
        atomicAdd(&g_count[b0], 1);
        atomicAdd(&g_count[b1], 1);
    }
    __syncthreads();
    if (warp == 0 && lane < NEXP) {
        float s = 0.f;
#pragma unroll
        for (int w = 0; w < 8; w++) s += sp[w][lane];
        g_partial[blockIdx.x * NEXP + lane] = s;
    }
}

// ---------------- 2: setup ---------------------------------------------------
__global__ void k_setup(float* __restrict__ out) {
    __shared__ float red[32][NEXP];
    __shared__ float auxp[NEXP];
    int t = threadIdx.x;
    {
        int e = t & 7, chunk = t >> 3;
        float s = 0.f;
        for (int b = 0; b < 32; b++) s += g_partial[(chunk * 32 + b) * NEXP + e];
        red[chunk][e] = s;
    }
    if (t == 0) {
        int off = 0, nt = 0;
        for (int e = 0; e < NEXP; e++) {
            g_cursor[e] = off;
            int tiles = (g_count[e] + 127) >> 7;
            for (int r = 0; r < tiles; r++) { g_tileE[nt] = e; g_tileR[nt] = off + r * 128; nt++; }
            off += tiles * 128;
        }
        g_numTiles = nt;
    }
    __syncthreads();
    if (t < NEXP) {
        float s = 0.f;
        for (int c = 0; c < 32; c++) s += red[c][t];
        float mean = s / (float)N_TOK;
        float frac = (float)g_count[t] / (float)N_TOK;
        auxp[t] = frac * mean;
    }
    __syncthreads();
    if (t == 0) {
        float s = 0.f;
        for (int e = 0; e < NEXP; e++) s += auxp[e];
        out[AUX_OFF] = (float)NEXP * s;
    }
}

// ---------------- 3: scatter -------------------------------------------------
__global__ void k_scatter() {
    int n = blockIdx.x * 256 + threadIdx.x;
    if (n >= N_TOK) return;
#pragma unroll
    for (int k = 0; k < KSEL; k++) {
        int e = g_tokE[n * 2 + k];
        int pos = atomicAdd(&g_cursor[e], 1);
        g_assign[pos] = n;
        g_t2p[n * 2 + k] = pos;
    }
}

// ---------------- 4: single-term fp16 mma.sync grouped GEMM ------------------
// C ~= Ah @ Bh. 128x256x32 tiles, 8 warps (4M x 2N), warp tile 32x128.
// Inner loop software-pipelines B-fragment ldmatrix between MMAs (double
// buffer) and hoists all A fragments to stage start, so the LSU fragment
// traffic (~640 cyc/stage SM-wide) overlaps the tensor pipe instead of
// serializing with it.
#define RS       80
#define BRS      528                 // 256 halves + 16B pad; 528 % 128 == 16
#define A_T      (128 * RS)          // 10240
#define B_T      (32 * BRS)          // 16896
#define OFF_AH   0
#define OFF_BH   A_T
#define STG      (A_T + B_T)         // 27136
#define SMEM_DYN (2 * STG)           // 54272

template<int PHASE>
__global__ void __launch_bounds__(256, 1)
k_mma(const float* __restrict__ x, const float* __restrict__ w) {
    constexpr int KDIM = (PHASE == 1) ? DDIM : HDIM;
    constexpr int NG   = (PHASE == 1) ? HDIM : DDIM;
    int tileIdx = blockIdx.y;
    if (tileIdx >= g_numTiles) return;

    extern __shared__ char smem[];
    __shared__ int aTok[128];
    uint32_t sb = smem_u32(smem);
    int tid = threadIdx.x, wid = tid >> 5, l = tid & 31;

    int e = g_tileE[tileIdx];
    int rowBase = g_tileR[tileIdx];
    int n0 = blockIdx.x * 256;

    if (PHASE == 1 && tid < 128) aTok[tid] = g_assign[rowBase + tid];
    __syncthreads();

    const float* Bg = w + (size_t)e * DDIM * HDIM + n0;

    // B loader geometry (fp32 source, hi-pack in-loop): 8 float4/thread/stage
    const float* bBase[8];
    uint32_t sB[8];
#pragma unroll
    for (int j = 0; j < 8; j++) {
        int lin = tid + j * 256;
        int kr = lin >> 6, nc4 = (lin & 63) << 2;
        bBase[j] = Bg + (size_t)kr * NG + nc4;
        sB[j] = kr * BRS + nc4 * 2;
    }

    // A loader geometry
    const float*  aBase[4];   // phase 1: fp32 x rows (gathered)
    uint32_t sA[4];
    const __half* aBaseH[2];  // phase 2: fp16 g_Hh rows (direct copy)
    uint32_t sA2[2];
    if (PHASE == 1) {
#pragma unroll
        for (int j = 0; j < 4; j++) {
            int lin = tid + j * 256;
            int r = lin >> 3, c4 = (lin & 7) << 2;
            aBase[j] = x + (size_t)aTok[r] * DDIM + c4;
            sA[j] = r * RS + c4 * 2;
        }
    } else {
#pragma unroll
        for (int j = 0; j < 2; j++) {
            int lin = tid + j * 256;
            int r = lin >> 2, c8 = (lin & 3) << 3;
            aBaseH[j] = g_Hh + (size_t)(rowBase + r) * HDIM + c8;
            sA2[j] = r * RS + c8 * 2;
        }
    }

    int warpRow = (wid >> 1) * 32;
    int warpCol = (wid & 1) * 128;

    float acc[2][16][4];
#pragma unroll
    for (int i = 0; i < 2; i++)
#pragma unroll
        for (int j = 0; j < 16; j++)
#pragma unroll
            for (int k = 0; k < 4; k++) acc[i][j][k] = 0.f;

    uint32_t aoffA = (warpRow + (l & 15)) * RS + ((l >> 4) << 4);
    uint32_t boffB = (l & 15) * BRS + ((l >> 4) << 4);

    const int S = KDIM / 32;

    float4 pa[4], pb[8];
    uint4  paU[2];
    // ---- prologue: load stage 0, convert+store into buf0 ----
    if (PHASE == 1) {
#pragma unroll
        for (int j = 0; j < 4; j++) pa[j] = *(const float4*)(aBase[j]);
    } else {
#pragma unroll
        for (int j = 0; j < 2; j++) paU[j] = *(const uint4*)(aBaseH[j]);
    }
#pragma unroll
    for (int j = 0; j < 8; j++) pb[j] = *(const float4*)(bBase[j]);

    if (PHASE == 1) {
#pragma unroll
        for (int j = 0; j < 4; j++) {
            uint32_t h0, h1;
            pack_hi4(pa[j], h0, h1);
            char* pH = smem + OFF_AH + sA[j];
            ((uint32_t*)pH)[0] = h0; ((uint32_t*)pH)[1] = h1;
        }
    } else {
#pragma unroll
        for (int j = 0; j < 2; j++)
            *(uint4*)(smem + OFF_AH + sA2[j]) = paU[j];
    }
#pragma unroll
    for (int j = 0; j < 8; j++) {
        uint32_t h0, h1;
        pack_hi4(pb[j], h0, h1);
        char* qH = smem + OFF_BH + sB[j];
        ((uint32_t*)qH)[0] = h0; ((uint32_t*)qH)[1] = h1;
    }
    __syncthreads();

    for (int i = 0; i < S; i++) {
        uint32_t stg = sb + (i & 1) * STG;
        char* nxt = smem + ((i + 1) & 1) * STG;

        // issue global loads for stage i+1 (latency hidden under MMAs below)
        if (i + 1 < S) {
            int k0 = (i + 1) * 32;
            if (PHASE == 1) {
#pragma unroll
                for (int j = 0; j < 4; j++) pa[j] = *(const float4*)(aBase[j] + k0);
            } else {
#pragma unroll
                for (int j = 0; j < 2; j++) paU[j] = *(const uint4*)(aBaseH[j] + k0);
            }
#pragma unroll
            for (int j = 0; j < 8; j++) pb[j] = *(const float4*)(bBase[j] + (size_t)k0 * NG);
        }

        // ---- MMA on stage i: pipelined fragment loads ----
        // All A fragments up front (both kh), B double-buffered: the ldmatrix
        // for iteration it+1 issues before the MMAs of iteration it.
        uint32_t ah[2][2][4];
#pragma unroll
        for (int kh = 0; kh < 2; kh++) {
            LDMX4(ah[kh][0][0], ah[kh][0][1], ah[kh][0][2], ah[kh][0][3],
                  stg + OFF_AH + aoffA + kh * 32);
            LDMX4(ah[kh][1][0], ah[kh][1][1], ah[kh][1][2], ah[kh][1][3],
                  stg + OFF_AH + aoffA + 16 * RS + kh * 32);
        }
        uint32_t bq[2][4];
        LDMX4T(bq[0][0], bq[0][1], bq[0][2], bq[0][3],
               stg + OFF_BH + boffB + warpCol * 2);
#pragma unroll
        for (int it = 0; it < 16; it++) {
            const int kh = it >> 3, p = it & 7;
            const int cur = it & 1, nb = cur ^ 1;
            if (it < 15) {
                const int it2 = it + 1;
                const int kh2 = it2 >> 3, p2 = it2 & 7;
                uint32_t bo2 = boffB + kh2 * (16 * BRS) + (warpCol + p2 * 16) * 2;
                LDMX4T(bq[nb][0], bq[nb][1], bq[nb][2], bq[nb][3], stg + OFF_BH + bo2);
            }
            MMA(acc[0][2*p][0], acc[0][2*p][1], acc[0][2*p][2], acc[0][2*p][3],
                ah[kh][0][0], ah[kh][0][1], ah[kh][0][2], ah[kh][0][3],
                bq[cur][0], bq[cur][1]);
            MMA(acc[1][2*p][0], acc[1][2*p][1], acc[1][2*p][2], acc[1][2*p][3],
                ah[kh][1][0], ah[kh][1][1], ah[kh][1][2], ah[kh][1][3],
                bq[cur][0], bq[cur][1]);
            MMA(acc[0][2*p+1][0], acc[0][2*p+1][1], acc[0][2*p+1][2], acc[0][2*p+1][3],
                ah[kh][0][0], ah[kh][0][1], ah[kh][0][2], ah[kh][0][3],
                bq[cur][2], bq[cur][3]);
            MMA(acc[1][2*p+1][0], acc[1][2*p+1][1], acc[1][2*p+1][2], acc[1][2*p+1][3],
                ah[kh][1][0], ah[kh][1][1], ah[kh][1][2], ah[kh][1][3],
                bq[cur][2], bq[cur][3]);
        }

        // convert + store stage i+1 into the other buffer
        if (i + 1 < S) {
            if (PHASE == 1) {
#pragma unroll
                for (int j = 0; j < 4; j++) {
                    uint32_t h0, h1;
                    pack_hi4(pa[j], h0, h1);
                    char* pH = nxt + OFF_AH + sA[j];
                    ((uint32_t*)pH)[0] = h0; ((uint32_t*)pH)[1] = h1;
                }
            } else {
#pragma unroll
                for (int j = 0; j < 2; j++)
                    *(uint4*)(nxt + OFF_AH + sA2[j]) = paU[j];
            }
#pragma unroll
            for (int j = 0; j < 8; j++) {
                uint32_t h0, h1;
                pack_hi4(pb[j], h0, h1);
                char* qH = nxt + OFF_BH + sB[j];
                ((uint32_t*)qH)[0] = h0; ((uint32_t*)qH)[1] = h1;
            }
        }
        __syncthreads();
    }

    // epilogue
    int qrow = l >> 2, qcol = (l & 3) * 2;
#pragma unroll
    for (int mf = 0; mf < 2; mf++) {
        int r0 = rowBase + warpRow + mf * 16 + qrow;
#pragma unroll
        for (int nf = 0; nf < 16; nf++) {
            int col = n0 + warpCol + nf * 8 + qcol;
            float c0 = acc[mf][nf][0], c1 = acc[mf][nf][1];
            float c2 = acc[mf][nf][2], c3 = acc[mf][nf][3];
            if (PHASE == 1) {
                uint32_t hp;
                PACK2(hp, gelu_exact(c0), gelu_exact(c1));
                *(uint32_t*)(g_Hh + (size_t)r0 * HDIM + col) = hp;
                PACK2(hp, gelu_exact(c2), gelu_exact(c3));
                *(uint32_t*)(g_Hh + (size_t)(r0 + 8) * HDIM + col) = hp;
            } else {
                *(float2*)(g_Ybuf + (size_t)r0 * DDIM + col)       = make_float2(c0, c1);
                *(float2*)(g_Ybuf + (size_t)(r0 + 8) * DDIM + col) = make_float2(c2, c3);
            }
        }
    }
}

// ---------------- 5: combine -------------------------------------------------
__global__ void k_combine(float* __restrict__ out) {
    int n = blockIdx.x;
    int t = threadIdx.x;
    int p0 = g_t2p[n * 2 + 0], p1 = g_t2p[n * 2 + 1];
    float q0 = g_tokQ[n * 2 + 0], q1 = g_tokQ[n * 2 + 1];
    int c = t * 4;
    float4 y0 = *(const float4*)(g_Ybuf + (size_t)p0 * DDIM + c);
    float4 y1 = *(const float4*)(g_Ybuf + (size_t)p1 * DDIM + c);
    float4 o;
    o.x = q0 * y0.x + q1 * y1.x;
    o.y = q0 * y0.y + q1 * y1.y;
    o.z = q0 * y0.z + q1 * y1.z;
    o.w = q0 * y0.w + q1 * y1.w;
    *(float4*)(out + OUT_OFF + (size_t)n * DDIM + c) = o;
}

// ---------------- launch -----------------------------------------------------
extern "C" void kernel_launch(void* const* d_in, const int* in_sizes, int n_in,
                              void* d_out, int out_size) {
    const float* x  = (const float*)d_in[0];
    const float* gw = (const float*)d_in[1];
    const float* w1 = (const float*)d_in[2];
    const float* w2 = (const float*)d_in[3];
    float* out = (float*)d_out;

    cudaFuncSetAttribute(k_mma<1>, cudaFuncAttributeMaxDynamicSharedMemorySize, SMEM_DYN);
    cudaFuncSetAttribute(k_mma<2>, cudaFuncAttributeMaxDynamicSharedMemorySize, SMEM_DYN);

    k_init<<<(PADROWS + 255) / 256, 256>>>();
    k_router<<<1024, 256>>>(x, gw, out);
    k_setup<<<1, 256>>>(out);
    k_scatter<<<N_TOK / 256, 256>>>();
    k_mma<1><<<dim3(HDIM / 256, MAX_TILES), 256, SMEM_DYN>>>(x, w1);
    k_mma<2><<<dim3(DDIM / 256, MAX_TILES), 256, SMEM_DYN>>>(x, w2);
    k_combine<<<N_TOK, 256>>>(out);
}